// round 1
// baseline (speedup 1.0000x reference)
#include <cuda_runtime.h>
#include <cuda_bf16.h>
#include <math.h>

// Problem constants (fixed by the dataset)
constexpr int Bc  = 2;
constexpr int Tc  = 2048;
constexpr int Dc  = 1024;
constexpr int Hc  = 16;
constexpr int HDc = 64;   // head dim
constexpr int Mc  = Bc * Tc;      // 4096 rows for the projection GEMMs

// ---------------------------------------------------------------------------
// Scratch (device globals; no allocations allowed)
// ---------------------------------------------------------------------------
__device__ float g_Q[Bc * Hc * Tc * HDc];   // head-split [B,H,T,HD]
__device__ float g_K[Bc * Hc * Tc * HDc];
__device__ float g_V[Bc * Hc * Tc * HDc];
__device__ float g_A[Bc * Tc * Dc];         // attention output, [B*T, D]

// ---------------------------------------------------------------------------
// SGEMM: Y = X @ W + bias
//   X: [M,K] row-major, W: [K,N] row-major, bias: [N]
//   HEADSPLIT=true  -> Y[((b*H + n/HD)*T + t)*HD + n%HD], m = b*T + t
//   HEADSPLIT=false -> Y[m*N + n]
// Tile: BM=BN=64, BK=16, 256 threads, 4x4 register tile per thread.
// ---------------------------------------------------------------------------
constexpr int BM = 64, BN = 64, BKK = 16;

template <bool HEADSPLIT>
__global__ __launch_bounds__(256)
void gemm64(const float* __restrict__ X, const float* __restrict__ W,
            const float* __restrict__ bias, float* __restrict__ Y,
            int M, int N, int K)
{
    __shared__ float Xs[BKK][BM];   // X tile, transposed: Xs[k][m]
    __shared__ float Ws[BKK][BN];   // W tile: Ws[k][n]

    const int tid = threadIdx.x;          // 0..255
    const int tx  = tid & 15;             // 0..15  -> n sub-tile
    const int ty  = tid >> 4;             // 0..15  -> m sub-tile
    const int m0  = blockIdx.y * BM;
    const int n0  = blockIdx.x * BN;

    float acc[4][4] = {};

    // load-index precompute
    const int xr = tid >> 2;              // row within BM (0..63)
    const int xc = (tid & 3) << 2;        // col within BK (0,4,8,12)
    const int wr = tid >> 4;              // row within BK (0..15)
    const int wc = (tid & 15) << 2;       // col within BN (0..60)

    for (int k0 = 0; k0 < K; k0 += BKK) {
        // X tile: 64x16, float4 per thread
        {
            float4 xv = *(const float4*)&X[(size_t)(m0 + xr) * K + k0 + xc];
            Xs[xc + 0][xr] = xv.x;
            Xs[xc + 1][xr] = xv.y;
            Xs[xc + 2][xr] = xv.z;
            Xs[xc + 3][xr] = xv.w;
        }
        // W tile: 16x64, float4 per thread
        {
            float4 wv = *(const float4*)&W[(size_t)(k0 + wr) * N + n0 + wc];
            *(float4*)&Ws[wr][wc] = wv;
        }
        __syncthreads();

        #pragma unroll
        for (int k = 0; k < BKK; k++) {
            float4 av = *(float4*)&Xs[k][ty << 2];
            float4 bv = *(float4*)&Ws[k][tx << 2];
            float a[4] = {av.x, av.y, av.z, av.w};
            float b[4] = {bv.x, bv.y, bv.z, bv.w};
            #pragma unroll
            for (int i = 0; i < 4; i++)
                #pragma unroll
                for (int j = 0; j < 4; j++)
                    acc[i][j] = fmaf(a[i], b[j], acc[i][j]);
        }
        __syncthreads();
    }

    // epilogue
    #pragma unroll
    for (int i = 0; i < 4; i++) {
        const int m = m0 + (ty << 2) + i;
        #pragma unroll
        for (int j = 0; j < 4; j++) {
            const int n = n0 + (tx << 2) + j;
            const float v = acc[i][j] + bias[n];
            if (HEADSPLIT) {
                const int b = m / Tc;
                const int t = m - b * Tc;
                const int h = n >> 6;          // n / HD
                const int d = n & (HDc - 1);   // n % HD
                Y[((((size_t)b * Hc + h) * Tc + t) << 6) + d] = v;
            } else {
                Y[(size_t)m * N + n] = v;
            }
        }
    }
}

// ---------------------------------------------------------------------------
// Flash attention (causal), fp32.
//   Q,K,V: [B*H, T, HD] ; O: [B*T, D] (merging heads back)
//   Block: 64 query rows, 64 threads (1 thread = 1 query row).
//   K/V tiles of 32 keys in smem; broadcast reads -> conflict-free & cheap.
// ---------------------------------------------------------------------------
constexpr int BQ = 64;
constexpr int BKT = 32;

__global__ __launch_bounds__(64)
void attn_kernel(const float* __restrict__ Q, const float* __restrict__ Kg,
                 const float* __restrict__ Vg, float* __restrict__ O)
{
    __shared__ float Qs[BQ][HDc + 4];   // padded: row stride 68 floats (16B-aligned, conflict-free)
    __shared__ float Ks[BKT][HDc];
    __shared__ float Vs[BKT][HDc];

    const int tid = threadIdx.x;        // 0..63, owns query row q0+tid
    const int bh  = blockIdx.y;         // 0..B*H-1
    const int q0  = blockIdx.x * BQ;
    const int b   = bh / Hc;
    const int h   = bh - b * Hc;
    const float scale = 0.125f;         // 1/sqrt(64)

    // Load Q tile (pre-scaled)
    for (int i = tid; i < BQ * HDc; i += 64) {
        const int r = i >> 6, c = i & 63;
        Qs[r][c] = Q[((size_t)bh * Tc + q0 + r) * HDc + c] * scale;
    }

    float acc[HDc];
    #pragma unroll
    for (int d = 0; d < HDc; d++) acc[d] = 0.f;
    float mrun = -INFINITY, lrun = 0.f;
    const int qg = q0 + tid;            // this thread's global query index

    for (int k0 = 0; k0 < q0 + BQ; k0 += BKT) {
        __syncthreads();   // prior tile fully consumed; also orders Qs on first iter
        // load K/V tiles: 32x64 each, float4 per lane-iter
        for (int i = tid; i < BKT * (HDc / 4); i += 64) {
            const int r = i >> 4, c4 = (i & 15) << 2;
            const size_t gbase = ((size_t)bh * Tc + k0 + r) * HDc + c4;
            *(float4*)&Ks[r][c4] = *(const float4*)&Kg[gbase];
            *(float4*)&Vs[r][c4] = *(const float4*)&Vg[gbase];
        }
        __syncthreads();

        // scores for this thread's row vs 32 keys
        float s[BKT];
        #pragma unroll
        for (int j = 0; j < BKT; j++) s[j] = 0.f;
        #pragma unroll
        for (int d4 = 0; d4 < HDc; d4 += 4) {
            const float4 q4 = *(float4*)&Qs[tid][d4];
            #pragma unroll 8
            for (int j = 0; j < BKT; j++) {
                const float4 k4 = *(float4*)&Ks[j][d4];
                s[j] = fmaf(q4.x, k4.x, s[j]);
                s[j] = fmaf(q4.y, k4.y, s[j]);
                s[j] = fmaf(q4.z, k4.z, s[j]);
                s[j] = fmaf(q4.w, k4.w, s[j]);
            }
        }

        // causal mask (only possible in the last two tiles of the loop)
        if (k0 + BKT - 1 > qg) {
            #pragma unroll
            for (int j = 0; j < BKT; j++)
                if (k0 + j > qg) s[j] = -INFINITY;
        }

        // online softmax update
        float tmax = s[0];
        #pragma unroll
        for (int j = 1; j < BKT; j++) tmax = fmaxf(tmax, s[j]);
        const float mnew = fmaxf(mrun, tmax);
        const float corr = __expf(mrun - mnew);
        lrun *= corr;
        #pragma unroll
        for (int d = 0; d < HDc; d++) acc[d] *= corr;
        mrun = mnew;

        #pragma unroll
        for (int j = 0; j < BKT; j++) {
            const float p = __expf(s[j] - mnew);   // masked -> exp(-inf)=0
            lrun += p;
            #pragma unroll
            for (int d4 = 0; d4 < HDc; d4 += 4) {
                const float4 v4 = *(float4*)&Vs[j][d4];
                acc[d4 + 0] = fmaf(p, v4.x, acc[d4 + 0]);
                acc[d4 + 1] = fmaf(p, v4.y, acc[d4 + 1]);
                acc[d4 + 2] = fmaf(p, v4.z, acc[d4 + 2]);
                acc[d4 + 3] = fmaf(p, v4.w, acc[d4 + 3]);
            }
        }
    }

    // epilogue: merge heads -> [B*T, D]
    const float inv_l = 1.f / lrun;
    const size_t obase = ((size_t)b * Tc + qg) * Dc + (size_t)h * HDc;
    #pragma unroll
    for (int d4 = 0; d4 < HDc; d4 += 4) {
        float4 o4;
        o4.x = acc[d4 + 0] * inv_l;
        o4.y = acc[d4 + 1] * inv_l;
        o4.z = acc[d4 + 2] * inv_l;
        o4.w = acc[d4 + 3] * inv_l;
        *(float4*)&O[obase + d4] = o4;
    }
}

// ---------------------------------------------------------------------------
// Launch
// ---------------------------------------------------------------------------
extern "C" void kernel_launch(void* const* d_in, const int* in_sizes, int n_in,
                              void* d_out, int out_size)
{
    const float* x  = (const float*)d_in[0];
    const float* Wq = (const float*)d_in[1];
    const float* bq = (const float*)d_in[2];
    const float* Wk = (const float*)d_in[3];
    const float* bk = (const float*)d_in[4];
    const float* Wv = (const float*)d_in[5];
    const float* bv = (const float*)d_in[6];
    const float* Wo = (const float*)d_in[7];
    const float* bo = (const float*)d_in[8];
    float* out = (float*)d_out;

    float *Qp, *Kp, *Vp, *Ap;
    cudaGetSymbolAddress((void**)&Qp, g_Q);
    cudaGetSymbolAddress((void**)&Kp, g_K);
    cudaGetSymbolAddress((void**)&Vp, g_V);
    cudaGetSymbolAddress((void**)&Ap, g_A);

    const dim3 gemmGrid(Dc / BN, Mc / BM);   // (16, 64)
    const dim3 gemmBlock(256);

    gemm64<true><<<gemmGrid, gemmBlock>>>(x, Wq, bq, Qp, Mc, Dc, Dc);
    gemm64<true><<<gemmGrid, gemmBlock>>>(x, Wk, bk, Kp, Mc, Dc, Dc);
    gemm64<true><<<gemmGrid, gemmBlock>>>(x, Wv, bv, Vp, Mc, Dc, Dc);

    const dim3 attnGrid(Tc / BQ, Bc * Hc);   // (32, 32)
    attn_kernel<<<attnGrid, 64>>>(Qp, Kp, Vp, Ap);

    gemm64<false><<<gemmGrid, gemmBlock>>>(Ap, Wo, bo, out, Mc, Dc, Dc);
}

// round 4
// speedup vs baseline: 1.1019x; 1.1019x over previous
#include <cuda_runtime.h>
#include <cuda_bf16.h>
#include <math.h>
#include <stdint.h>

// Problem constants
constexpr int Bc  = 2;
constexpr int Tc  = 2048;
constexpr int Dc  = 1024;
constexpr int Hc  = 16;
constexpr int HDc = 64;
constexpr int Mc  = Bc * Tc;      // 4096

// ---------------------------------------------------------------------------
// Scratch (device globals; no allocations allowed)
// ---------------------------------------------------------------------------
__device__ float g_Xhi[Mc * Dc];
__device__ float g_Xlo[Mc * Dc];
__device__ float g_Q[Bc * Hc * Tc * HDc];
__device__ float g_K[Bc * Hc * Tc * HDc];
__device__ float g_V[Bc * Hc * Tc * HDc];
__device__ float g_Ahi[Bc * Tc * Dc];
__device__ float g_Alo[Bc * Tc * Dc];
__device__ float g_Wthi[4 * Dc * Dc];   // transposed weights [N,K], hi part
__device__ float g_Wtlo[4 * Dc * Dc];   // lo part

// ---------------------------------------------------------------------------
// Helpers
// ---------------------------------------------------------------------------
__device__ __forceinline__ float tf32r(float x) {
    uint32_t r;
    asm("cvt.rna.tf32.f32 %0, %1;" : "=r"(r) : "f"(x));
    return __uint_as_float(r);
}

__device__ __forceinline__ uint32_t smem_to_u32(const void* p) {
    uint32_t a;
    asm("{ .reg .u64 t; cvta.to.shared.u64 t, %1; cvt.u32.u64 %0, t; }" : "=r"(a) : "l"(p));
    return a;
}

__device__ __forceinline__ void cp_async16(uint32_t saddr, const void* gaddr) {
    asm volatile("cp.async.cg.shared.global [%0], [%1], 16;" :: "r"(saddr), "l"(gaddr));
}
__device__ __forceinline__ void cp_commit() {
    asm volatile("cp.async.commit_group;" ::: "memory");
}
template <int N>
__device__ __forceinline__ void cp_wait() {
    asm volatile("cp.async.wait_group %0;" :: "n"(N) : "memory");
}

// tf32 m16n8k8 mma.sync
__device__ __forceinline__ void mma_tf32(float* d, const uint32_t* a, const uint32_t* b) {
    asm volatile(
        "mma.sync.aligned.m16n8k8.row.col.f32.tf32.tf32.f32 "
        "{%0,%1,%2,%3}, {%4,%5,%6,%7}, {%8,%9}, {%0,%1,%2,%3};"
        : "+f"(d[0]), "+f"(d[1]), "+f"(d[2]), "+f"(d[3])
        : "r"(a[0]), "r"(a[1]), "r"(a[2]), "r"(a[3]), "r"(b[0]), "r"(b[1]));
}

// ---------------------------------------------------------------------------
// Prep: split float array into tf32 hi/lo (float4 per thread)
// ---------------------------------------------------------------------------
__global__ __launch_bounds__(256)
void split_tf32_kernel(const float* __restrict__ in, float* __restrict__ hi,
                       float* __restrict__ lo, int n4)
{
    int i = blockIdx.x * 256 + threadIdx.x;
    if (i < n4) {
        float4 v = ((const float4*)in)[i];
        float4 h, l;
        h.x = tf32r(v.x); l.x = tf32r(v.x - h.x);
        h.y = tf32r(v.y); l.y = tf32r(v.y - h.y);
        h.z = tf32r(v.z); l.z = tf32r(v.z - h.z);
        h.w = tf32r(v.w); l.w = tf32r(v.w - h.w);
        ((float4*)hi)[i] = h;
        ((float4*)lo)[i] = l;
    }
}

// ---------------------------------------------------------------------------
// Weight transpose + split: Wt_{hi,lo}[n][k] = split(W[k][n])  (4 matrices)
// ---------------------------------------------------------------------------
__global__ __launch_bounds__(256)
void transpose4_split(const float* __restrict__ W0, const float* __restrict__ W1,
                      const float* __restrict__ W2, const float* __restrict__ W3,
                      float* __restrict__ Thi, float* __restrict__ Tlo)
{
    __shared__ float tile[32][33];
    const int z = blockIdx.z;
    const float* W = (z == 0) ? W0 : (z == 1) ? W1 : (z == 2) ? W2 : W3;
    const size_t zoff = (size_t)z * Dc * Dc;

    const int tx = threadIdx.x, ty = threadIdx.y;
    int x = blockIdx.x * 32 + tx;
    int y = blockIdx.y * 32 + ty;
    #pragma unroll
    for (int j = 0; j < 32; j += 8)
        tile[ty + j][tx] = W[(size_t)(y + j) * Dc + x];
    __syncthreads();
    x = blockIdx.y * 32 + tx;
    y = blockIdx.x * 32 + ty;
    #pragma unroll
    for (int j = 0; j < 32; j += 8) {
        const float v = tile[tx][ty + j];
        const float h = tf32r(v);
        Thi[zoff + (size_t)(y + j) * Dc + x] = h;
        Tlo[zoff + (size_t)(y + j) * Dc + x] = tf32r(v - h);
    }
}

// ---------------------------------------------------------------------------
// 3xTF32 mma.sync GEMM:  Y = X @ Wt^T + bias   (fp32-accurate)
//   Xhi/Xlo : [4096, 1024] row-major ; Wthi/Wtlo : [1024, 1024] = W^T
// CTA tile 128x128, BK=32, 2-stage cp.async, 8 warps (2m x 4n), warp 64x32.
// smem/stage: 4 tiles (Ahi,Alo,Bhi,Blo) of 128x36 floats = 73728 B; x2 stages.
// ---------------------------------------------------------------------------
constexpr int BM = 128, BN = 128, BKC = 32;
constexpr int NCH = Dc / BKC;            // 32
constexpr int SST = BKC + 4;             // 36 floats row stride (conflict-free frags)
constexpr int TILE_F = BM * SST;         // 4608 floats
constexpr int STAGE_F = 4 * TILE_F;      // Ahi, Alo, Bhi, Blo
constexpr int GEMM_SMEM = 2 * STAGE_F * 4;  // 147456 B

template <bool HEADSPLIT>
__global__ __launch_bounds__(256, 1)
void gemm_3xtf32(const float* __restrict__ Xhi, const float* __restrict__ Xlo,
                 const float* __restrict__ Whi, const float* __restrict__ Wlo,
                 const float* __restrict__ bias, float* __restrict__ Y)
{
    extern __shared__ __align__(16) float smem[];
    const uint32_t sb = smem_to_u32(smem);
    const int tid = threadIdx.x;
    const int wid = tid >> 5, lane = tid & 31;
    const int g = lane >> 2, tg = lane & 3;
    const int wm = wid & 1;
    const int wn = wid >> 1;
    const int m0 = blockIdx.y * BM;
    const int n0 = blockIdx.x * BN;

    // async-load one k-chunk (4 tiles) into stage s
    auto load_chunk = [&](int k, int s) {
        const uint32_t sbase = sb + (uint32_t)s * STAGE_F * 4;
        const size_t aoff = (size_t)m0 * Dc + k * BKC;
        const size_t boff = (size_t)n0 * Dc + k * BKC;
        const float* srcs[4] = {Xhi + aoff, Xlo + aoff, Whi + boff, Wlo + boff};
        #pragma unroll
        for (int t = 0; t < 4; t++) {
            const float* gsrc = srcs[t];
            const uint32_t tbase = sbase + (uint32_t)t * TILE_F * 4;
            #pragma unroll
            for (int i = 0; i < 4; i++) {
                const int u = i * 256 + tid;              // 0..1023
                const int row = u >> 3, kc = (u & 7) << 2;
                cp_async16(tbase + (uint32_t)(row * SST + kc) * 4,
                           gsrc + (size_t)row * Dc + kc);
            }
        }
        cp_commit();
    };

    float acc[4][4][4] = {};

    load_chunk(0, 0);
    load_chunk(1, 1);

    for (int k = 0; k < NCH; k++) {
        const int s = k & 1;
        cp_wait<1>();
        __syncthreads();

        const float* Ahi = smem + s * STAGE_F;
        const float* Alo = Ahi + TILE_F;
        const float* Bhi = Alo + TILE_F;
        const float* Blo = Bhi + TILE_F;

        #pragma unroll
        for (int kk = 0; kk < 4; kk++) {
            const int kb = kk * 8;
            uint32_t ah[4][4], al[4][4], bh[4][2], bl[4][2];
            #pragma unroll
            for (int mi = 0; mi < 4; mi++) {
                const int r = wm * 64 + mi * 16;
                const int i00 = (r + g) * SST + kb + tg;
                const int i10 = (r + g + 8) * SST + kb + tg;
                ah[mi][0] = __float_as_uint(Ahi[i00]);
                ah[mi][1] = __float_as_uint(Ahi[i10]);
                ah[mi][2] = __float_as_uint(Ahi[i00 + 4]);
                ah[mi][3] = __float_as_uint(Ahi[i10 + 4]);
                al[mi][0] = __float_as_uint(Alo[i00]);
                al[mi][1] = __float_as_uint(Alo[i10]);
                al[mi][2] = __float_as_uint(Alo[i00 + 4]);
                al[mi][3] = __float_as_uint(Alo[i10 + 4]);
            }
            #pragma unroll
            for (int ni = 0; ni < 4; ni++) {
                const int r = wn * 32 + ni * 8;
                const int i0 = (r + g) * SST + kb + tg;
                bh[ni][0] = __float_as_uint(Bhi[i0]);
                bh[ni][1] = __float_as_uint(Bhi[i0 + 4]);
                bl[ni][0] = __float_as_uint(Blo[i0]);
                bl[ni][1] = __float_as_uint(Blo[i0 + 4]);
            }
            #pragma unroll
            for (int mi = 0; mi < 4; mi++)
                #pragma unroll
                for (int ni = 0; ni < 4; ni++) {
                    mma_tf32(acc[mi][ni], al[mi], bh[ni]);   // lo*hi
                    mma_tf32(acc[mi][ni], ah[mi], bl[ni]);   // hi*lo
                    mma_tf32(acc[mi][ni], ah[mi], bh[ni]);   // hi*hi (last: largest term)
                }
        }

        __syncthreads();
        if (k + 2 < NCH) load_chunk(k + 2, s);
    }

    // epilogue
    #pragma unroll
    for (int mi = 0; mi < 4; mi++) {
        const int row0 = m0 + wm * 64 + mi * 16 + g;
        #pragma unroll
        for (int ni = 0; ni < 4; ni++) {
            const int col = n0 + wn * 32 + ni * 8 + 2 * tg;
            const float2 bv = *(const float2*)&bias[col];
            float2 v0, v1;
            v0.x = acc[mi][ni][0] + bv.x;  v0.y = acc[mi][ni][1] + bv.y;
            v1.x = acc[mi][ni][2] + bv.x;  v1.y = acc[mi][ni][3] + bv.y;
            if (HEADSPLIT) {
                const int h = col >> 6, d0 = col & 63;
                const int b0i = row0 >> 11, t0 = row0 & 2047;
                *(float2*)(Y + ((((size_t)b0i * Hc + h) * Tc + t0) << 6) + d0) = v0;
                const int row1 = row0 + 8;
                const int b1i = row1 >> 11, t1 = row1 & 2047;
                *(float2*)(Y + ((((size_t)b1i * Hc + h) * Tc + t1) << 6) + d0) = v1;
            } else {
                *(float2*)(Y + (size_t)row0 * Dc + col) = v0;
                *(float2*)(Y + (size_t)(row0 + 8) * Dc + col) = v1;
            }
        }
    }
}

// ---------------------------------------------------------------------------
// Flash attention (R1-proven); epilogue emits hi/lo split for the O-GEMM
// ---------------------------------------------------------------------------
constexpr int BQ = 64;
constexpr int BKT = 32;

__global__ __launch_bounds__(64)
void attn_kernel(const float* __restrict__ Q, const float* __restrict__ Kg,
                 const float* __restrict__ Vg,
                 float* __restrict__ Ohi, float* __restrict__ Olo)
{
    __shared__ float Qs[BQ][HDc + 4];
    __shared__ float Ks[BKT][HDc];
    __shared__ float Vs[BKT][HDc];

    const int tid = threadIdx.x;
    const int bh  = blockIdx.y;
    const int q0  = blockIdx.x * BQ;
    const int b   = bh / Hc;
    const int h   = bh - b * Hc;
    const float scale = 0.125f;

    for (int i = tid; i < BQ * HDc; i += 64) {
        const int r = i >> 6, c = i & 63;
        Qs[r][c] = Q[((size_t)bh * Tc + q0 + r) * HDc + c] * scale;
    }

    float acc[HDc];
    #pragma unroll
    for (int d = 0; d < HDc; d++) acc[d] = 0.f;
    float mrun = -INFINITY, lrun = 0.f;
    const int qg = q0 + tid;

    for (int k0 = 0; k0 < q0 + BQ; k0 += BKT) {
        __syncthreads();
        for (int i = tid; i < BKT * (HDc / 4); i += 64) {
            const int r = i >> 4, c4 = (i & 15) << 2;
            const size_t gbase = ((size_t)bh * Tc + k0 + r) * HDc + c4;
            *(float4*)&Ks[r][c4] = *(const float4*)&Kg[gbase];
            *(float4*)&Vs[r][c4] = *(const float4*)&Vg[gbase];
        }
        __syncthreads();

        float s[BKT];
        #pragma unroll
        for (int j = 0; j < BKT; j++) s[j] = 0.f;
        #pragma unroll
        for (int d4 = 0; d4 < HDc; d4 += 4) {
            const float4 q4 = *(float4*)&Qs[tid][d4];
            #pragma unroll 8
            for (int j = 0; j < BKT; j++) {
                const float4 k4 = *(float4*)&Ks[j][d4];
                s[j] = fmaf(q4.x, k4.x, s[j]);
                s[j] = fmaf(q4.y, k4.y, s[j]);
                s[j] = fmaf(q4.z, k4.z, s[j]);
                s[j] = fmaf(q4.w, k4.w, s[j]);
            }
        }

        if (k0 + BKT - 1 > qg) {
            #pragma unroll
            for (int j = 0; j < BKT; j++)
                if (k0 + j > qg) s[j] = -INFINITY;
        }

        float tmax = s[0];
        #pragma unroll
        for (int j = 1; j < BKT; j++) tmax = fmaxf(tmax, s[j]);
        const float mnew = fmaxf(mrun, tmax);
        const float corr = __expf(mrun - mnew);
        lrun *= corr;
        #pragma unroll
        for (int d = 0; d < HDc; d++) acc[d] *= corr;
        mrun = mnew;

        #pragma unroll
        for (int j = 0; j < BKT; j++) {
            const float p = __expf(s[j] - mnew);
            lrun += p;
            #pragma unroll
            for (int d4 = 0; d4 < HDc; d4 += 4) {
                const float4 v4 = *(float4*)&Vs[j][d4];
                acc[d4 + 0] = fmaf(p, v4.x, acc[d4 + 0]);
                acc[d4 + 1] = fmaf(p, v4.y, acc[d4 + 1]);
                acc[d4 + 2] = fmaf(p, v4.z, acc[d4 + 2]);
                acc[d4 + 3] = fmaf(p, v4.w, acc[d4 + 3]);
            }
        }
    }

    const float inv_l = 1.f / lrun;
    const size_t obase = ((size_t)b * Tc + qg) * Dc + (size_t)h * HDc;
    #pragma unroll
    for (int d4 = 0; d4 < HDc; d4 += 4) {
        float4 oh, ol;
        float v;
        v = acc[d4 + 0] * inv_l; oh.x = tf32r(v); ol.x = tf32r(v - oh.x);
        v = acc[d4 + 1] * inv_l; oh.y = tf32r(v); ol.y = tf32r(v - oh.y);
        v = acc[d4 + 2] * inv_l; oh.z = tf32r(v); ol.z = tf32r(v - oh.z);
        v = acc[d4 + 3] * inv_l; oh.w = tf32r(v); ol.w = tf32r(v - oh.w);
        *(float4*)&Ohi[obase + d4] = oh;
        *(float4*)&Olo[obase + d4] = ol;
    }
}

// ---------------------------------------------------------------------------
// Launch
// ---------------------------------------------------------------------------
extern "C" void kernel_launch(void* const* d_in, const int* in_sizes, int n_in,
                              void* d_out, int out_size)
{
    const float* x  = (const float*)d_in[0];
    const float* Wq = (const float*)d_in[1];
    const float* bq = (const float*)d_in[2];
    const float* Wk = (const float*)d_in[3];
    const float* bk = (const float*)d_in[4];
    const float* Wv = (const float*)d_in[5];
    const float* bv = (const float*)d_in[6];
    const float* Wo = (const float*)d_in[7];
    const float* bo = (const float*)d_in[8];
    float* out = (float*)d_out;

    float *Xhi, *Xlo, *Qp, *Kp, *Vp, *Ahi, *Alo, *Whi, *Wlo;
    cudaGetSymbolAddress((void**)&Xhi, g_Xhi);
    cudaGetSymbolAddress((void**)&Xlo, g_Xlo);
    cudaGetSymbolAddress((void**)&Qp, g_Q);
    cudaGetSymbolAddress((void**)&Kp, g_K);
    cudaGetSymbolAddress((void**)&Vp, g_V);
    cudaGetSymbolAddress((void**)&Ahi, g_Ahi);
    cudaGetSymbolAddress((void**)&Alo, g_Alo);
    cudaGetSymbolAddress((void**)&Whi, g_Wthi);
    cudaGetSymbolAddress((void**)&Wlo, g_Wtlo);

    cudaFuncSetAttribute(gemm_3xtf32<true>,  cudaFuncAttributeMaxDynamicSharedMemorySize, GEMM_SMEM);
    cudaFuncSetAttribute(gemm_3xtf32<false>, cudaFuncAttributeMaxDynamicSharedMemorySize, GEMM_SMEM);

    // 1) prep: split X; transpose+split weights
    const int n4 = Mc * Dc / 4;
    split_tf32_kernel<<<(n4 + 255) / 256, 256>>>(x, Xhi, Xlo, n4);
    transpose4_split<<<dim3(32, 32, 4), dim3(32, 8)>>>(Wq, Wk, Wv, Wo, Whi, Wlo);

    // 2) Q/K/V projections (3xTF32 tensor cores)
    const dim3 gg(Dc / BN, Mc / BM);   // (8, 32)
    const size_t DD = (size_t)Dc * Dc;
    gemm_3xtf32<true><<<gg, 256, GEMM_SMEM>>>(Xhi, Xlo, Whi + 0 * DD, Wlo + 0 * DD, bq, Qp);
    gemm_3xtf32<true><<<gg, 256, GEMM_SMEM>>>(Xhi, Xlo, Whi + 1 * DD, Wlo + 1 * DD, bk, Kp);
    gemm_3xtf32<true><<<gg, 256, GEMM_SMEM>>>(Xhi, Xlo, Whi + 2 * DD, Wlo + 2 * DD, bv, Vp);

    // 3) attention (fp32, emits hi/lo for O-GEMM)
    const dim3 ag(Tc / BQ, Bc * Hc);
    attn_kernel<<<ag, 64>>>(Qp, Kp, Vp, Ahi, Alo);

    // 4) output projection -> d_out
    gemm_3xtf32<false><<<gg, 256, GEMM_SMEM>>>(Ahi, Alo, Whi + 3 * DD, Wlo + 3 * DD, bo, out);
}

// round 6
// speedup vs baseline: 3.1776x; 2.8839x over previous
#include <cuda_runtime.h>
#include <cuda_bf16.h>
#include <math.h>
#include <stdint.h>

// Problem constants
constexpr int Bc  = 2;
constexpr int Tc  = 2048;
constexpr int Dc  = 1024;
constexpr int Hc  = 16;
constexpr int HDc = 64;
constexpr int Mc  = Bc * Tc;      // 4096

// ---------------------------------------------------------------------------
// Scratch (device globals; no allocations allowed)
// ---------------------------------------------------------------------------
__device__ float g_Xhi[Mc * Dc];
__device__ float g_Xlo[Mc * Dc];
__device__ float g_Q[Bc * Hc * Tc * HDc];
__device__ float g_K[Bc * Hc * Tc * HDc];
__device__ float g_V[Bc * Hc * Tc * HDc];
__device__ float g_Khi[Bc * Hc * Tc * HDc];
__device__ float g_Klo[Bc * Hc * Tc * HDc];
__device__ float g_Vthi[Bc * Hc * Tc * HDc];   // transposed: [bh][d][t]
__device__ float g_Vtlo[Bc * Hc * Tc * HDc];
__device__ float g_Ahi[Bc * Tc * Dc];
__device__ float g_Alo[Bc * Tc * Dc];
__device__ float g_Wthi[4 * Dc * Dc];
__device__ float g_Wtlo[4 * Dc * Dc];

// ---------------------------------------------------------------------------
// Helpers
// ---------------------------------------------------------------------------
__device__ __forceinline__ float tf32r(float x) {
    uint32_t r;
    asm("cvt.rna.tf32.f32 %0, %1;" : "=r"(r) : "f"(x));
    return __uint_as_float(r);
}

__device__ __forceinline__ uint32_t smem_to_u32(const void* p) {
    uint32_t a;
    asm("{ .reg .u64 t; cvta.to.shared.u64 t, %1; cvt.u32.u64 %0, t; }" : "=r"(a) : "l"(p));
    return a;
}

__device__ __forceinline__ void cp_async16(uint32_t saddr, const void* gaddr) {
    asm volatile("cp.async.cg.shared.global [%0], [%1], 16;" :: "r"(saddr), "l"(gaddr));
}
__device__ __forceinline__ void cp_commit() {
    asm volatile("cp.async.commit_group;" ::: "memory");
}
template <int N>
__device__ __forceinline__ void cp_wait() {
    asm volatile("cp.async.wait_group %0;" :: "n"(N) : "memory");
}

// tf32 m16n8k8 mma.sync
__device__ __forceinline__ void mma_tf32(float* d, const uint32_t* a, const uint32_t* b) {
    asm volatile(
        "mma.sync.aligned.m16n8k8.row.col.f32.tf32.tf32.f32 "
        "{%0,%1,%2,%3}, {%4,%5,%6,%7}, {%8,%9}, {%0,%1,%2,%3};"
        : "+f"(d[0]), "+f"(d[1]), "+f"(d[2]), "+f"(d[3])
        : "r"(a[0]), "r"(a[1]), "r"(a[2]), "r"(a[3]), "r"(b[0]), "r"(b[1]));
}

// ---------------------------------------------------------------------------
// Prep: split float array into tf32 hi/lo (float4 per thread)
// ---------------------------------------------------------------------------
__global__ __launch_bounds__(256)
void split_tf32_kernel(const float* __restrict__ in, float* __restrict__ hi,
                       float* __restrict__ lo, int n4)
{
    int i = blockIdx.x * 256 + threadIdx.x;
    if (i < n4) {
        float4 v = ((const float4*)in)[i];
        float4 h, l;
        h.x = tf32r(v.x); l.x = tf32r(v.x - h.x);
        h.y = tf32r(v.y); l.y = tf32r(v.y - h.y);
        h.z = tf32r(v.z); l.z = tf32r(v.z - h.z);
        h.w = tf32r(v.w); l.w = tf32r(v.w - h.w);
        ((float4*)hi)[i] = h;
        ((float4*)lo)[i] = l;
    }
}

// ---------------------------------------------------------------------------
// Prep: per-head transpose + split of V: Vt[bh][d][t] = split(V[bh][t][d])
// ---------------------------------------------------------------------------
__global__ __launch_bounds__(256)
void trans_split_V(const float* __restrict__ V, float* __restrict__ Thi,
                   float* __restrict__ Tlo)
{
    __shared__ float tile[32][33];
    const int bh = blockIdx.z;
    const int t0 = blockIdx.x * 32, d0 = blockIdx.y * 32;
    const int tx = threadIdx.x, ty = threadIdx.y;
    const float* src = V + (size_t)bh * Tc * HDc;
    #pragma unroll
    for (int j = 0; j < 32; j += 8)
        tile[ty + j][tx] = src[(size_t)(t0 + ty + j) * HDc + d0 + tx];
    __syncthreads();
    float* dh = Thi + (size_t)bh * HDc * Tc;
    float* dl = Tlo + (size_t)bh * HDc * Tc;
    #pragma unroll
    for (int j = 0; j < 32; j += 8) {
        const float v = tile[tx][ty + j];
        const float h = tf32r(v);
        dh[(size_t)(d0 + ty + j) * Tc + t0 + tx] = h;
        dl[(size_t)(d0 + ty + j) * Tc + t0 + tx] = tf32r(v - h);
    }
}

// ---------------------------------------------------------------------------
// Weight transpose + split: Wt_{hi,lo}[n][k] = split(W[k][n])  (4 matrices)
// ---------------------------------------------------------------------------
__global__ __launch_bounds__(256)
void transpose4_split(const float* __restrict__ W0, const float* __restrict__ W1,
                      const float* __restrict__ W2, const float* __restrict__ W3,
                      float* __restrict__ Thi, float* __restrict__ Tlo)
{
    __shared__ float tile[32][33];
    const int z = blockIdx.z;
    const float* W = (z == 0) ? W0 : (z == 1) ? W1 : (z == 2) ? W2 : W3;
    const size_t zoff = (size_t)z * Dc * Dc;

    const int tx = threadIdx.x, ty = threadIdx.y;
    int x = blockIdx.x * 32 + tx;
    int y = blockIdx.y * 32 + ty;
    #pragma unroll
    for (int j = 0; j < 32; j += 8)
        tile[ty + j][tx] = W[(size_t)(y + j) * Dc + x];
    __syncthreads();
    x = blockIdx.y * 32 + tx;
    y = blockIdx.x * 32 + ty;
    #pragma unroll
    for (int j = 0; j < 32; j += 8) {
        const float v = tile[tx][ty + j];
        const float h = tf32r(v);
        Thi[zoff + (size_t)(y + j) * Dc + x] = h;
        Tlo[zoff + (size_t)(y + j) * Dc + x] = tf32r(v - h);
    }
}

// ---------------------------------------------------------------------------
// 3xTF32 mma.sync GEMM (R4-proven)
// ---------------------------------------------------------------------------
constexpr int BM = 128, BN = 128, BKC = 32;
constexpr int NCH = Dc / BKC;
constexpr int SST = BKC + 4;
constexpr int TILE_F = BM * SST;
constexpr int STAGE_F = 4 * TILE_F;
constexpr int GEMM_SMEM = 2 * STAGE_F * 4;

template <bool HEADSPLIT>
__global__ __launch_bounds__(256, 1)
void gemm_3xtf32(const float* __restrict__ Xhi, const float* __restrict__ Xlo,
                 const float* __restrict__ Whi, const float* __restrict__ Wlo,
                 const float* __restrict__ bias, float* __restrict__ Y)
{
    extern __shared__ __align__(16) float smem[];
    const uint32_t sb = smem_to_u32(smem);
    const int tid = threadIdx.x;
    const int wid = tid >> 5, lane = tid & 31;
    const int g = lane >> 2, tg = lane & 3;
    const int wm = wid & 1;
    const int wn = wid >> 1;
    const int m0 = blockIdx.y * BM;
    const int n0 = blockIdx.x * BN;

    auto load_chunk = [&](int k, int s) {
        const uint32_t sbase = sb + (uint32_t)s * STAGE_F * 4;
        const size_t aoff = (size_t)m0 * Dc + k * BKC;
        const size_t boff = (size_t)n0 * Dc + k * BKC;
        const float* srcs[4] = {Xhi + aoff, Xlo + aoff, Whi + boff, Wlo + boff};
        #pragma unroll
        for (int t = 0; t < 4; t++) {
            const float* gsrc = srcs[t];
            const uint32_t tbase = sbase + (uint32_t)t * TILE_F * 4;
            #pragma unroll
            for (int i = 0; i < 4; i++) {
                const int u = i * 256 + tid;
                const int row = u >> 3, kc = (u & 7) << 2;
                cp_async16(tbase + (uint32_t)(row * SST + kc) * 4,
                           gsrc + (size_t)row * Dc + kc);
            }
        }
        cp_commit();
    };

    float acc[4][4][4] = {};

    load_chunk(0, 0);
    load_chunk(1, 1);

    for (int k = 0; k < NCH; k++) {
        const int s = k & 1;
        cp_wait<1>();
        __syncthreads();

        const float* Ahi = smem + s * STAGE_F;
        const float* Alo = Ahi + TILE_F;
        const float* Bhi = Alo + TILE_F;
        const float* Blo = Bhi + TILE_F;

        #pragma unroll
        for (int kk = 0; kk < 4; kk++) {
            const int kb = kk * 8;
            uint32_t ah[4][4], al[4][4], bh[4][2], bl[4][2];
            #pragma unroll
            for (int mi = 0; mi < 4; mi++) {
                const int r = wm * 64 + mi * 16;
                const int i00 = (r + g) * SST + kb + tg;
                const int i10 = (r + g + 8) * SST + kb + tg;
                ah[mi][0] = __float_as_uint(Ahi[i00]);
                ah[mi][1] = __float_as_uint(Ahi[i10]);
                ah[mi][2] = __float_as_uint(Ahi[i00 + 4]);
                ah[mi][3] = __float_as_uint(Ahi[i10 + 4]);
                al[mi][0] = __float_as_uint(Alo[i00]);
                al[mi][1] = __float_as_uint(Alo[i10]);
                al[mi][2] = __float_as_uint(Alo[i00 + 4]);
                al[mi][3] = __float_as_uint(Alo[i10 + 4]);
            }
            #pragma unroll
            for (int ni = 0; ni < 4; ni++) {
                const int r = wn * 32 + ni * 8;
                const int i0 = (r + g) * SST + kb + tg;
                bh[ni][0] = __float_as_uint(Bhi[i0]);
                bh[ni][1] = __float_as_uint(Bhi[i0 + 4]);
                bl[ni][0] = __float_as_uint(Blo[i0]);
                bl[ni][1] = __float_as_uint(Blo[i0 + 4]);
            }
            #pragma unroll
            for (int mi = 0; mi < 4; mi++)
                #pragma unroll
                for (int ni = 0; ni < 4; ni++) {
                    mma_tf32(acc[mi][ni], al[mi], bh[ni]);
                    mma_tf32(acc[mi][ni], ah[mi], bl[ni]);
                    mma_tf32(acc[mi][ni], ah[mi], bh[ni]);
                }
        }

        __syncthreads();
        if (k + 2 < NCH) load_chunk(k + 2, s);
    }

    #pragma unroll
    for (int mi = 0; mi < 4; mi++) {
        const int row0 = m0 + wm * 64 + mi * 16 + g;
        #pragma unroll
        for (int ni = 0; ni < 4; ni++) {
            const int col = n0 + wn * 32 + ni * 8 + 2 * tg;
            const float2 bv = *(const float2*)&bias[col];
            float2 v0, v1;
            v0.x = acc[mi][ni][0] + bv.x;  v0.y = acc[mi][ni][1] + bv.y;
            v1.x = acc[mi][ni][2] + bv.x;  v1.y = acc[mi][ni][3] + bv.y;
            if (HEADSPLIT) {
                const int h = col >> 6, d0 = col & 63;
                const int b0i = row0 >> 11, t0 = row0 & 2047;
                *(float2*)(Y + ((((size_t)b0i * Hc + h) * Tc + t0) << 6) + d0) = v0;
                const int row1 = row0 + 8;
                const int b1i = row1 >> 11, t1 = row1 & 2047;
                *(float2*)(Y + ((((size_t)b1i * Hc + h) * Tc + t1) << 6) + d0) = v1;
            } else {
                *(float2*)(Y + (size_t)row0 * Dc + col) = v0;
                *(float2*)(Y + (size_t)(row0 + 8) * Dc + col) = v1;
            }
        }
    }
}

// ---------------------------------------------------------------------------
// mma.sync flash attention (3xTF32 for QK^T and PV), causal.
//   CTA: 64 queries, 4 warps (16 rows each); key tiles of 32, 2-stage cp.async.
// ---------------------------------------------------------------------------
constexpr int AQ  = 64;
constexpr int AKT = 32;
constexpr int KSTr = 68;                 // K tile smem row stride (floats)
constexpr int VSTr = 36;                 // Vt tile smem row stride
constexpr int KTILE_F = AKT * KSTr;      // 2176
constexpr int VTILE_F = HDc * VSTr;      // 2304
constexpr int ASTAGE_F = 2 * KTILE_F + 2 * VTILE_F;  // 8960
constexpr int P_OFF = 2 * ASTAGE_F;      // 17920
constexpr int ATTN_SMEM = (P_OFF + 4 * 16 * 36) * 4; // 80896 B

__global__ __launch_bounds__(128, 1)
void attn_mma(const float* __restrict__ Q,
              const float* __restrict__ Khi, const float* __restrict__ Klo,
              const float* __restrict__ Vthi, const float* __restrict__ Vtlo,
              float* __restrict__ Ohi, float* __restrict__ Olo)
{
    extern __shared__ __align__(16) float as_[];
    const uint32_t sb = smem_to_u32(as_);
    const int tid = threadIdx.x, wid = tid >> 5, lane = tid & 31;
    const int g = lane >> 2, tg = lane & 3;
    const int bh = blockIdx.y;
    const int q0 = (int)(gridDim.x - 1 - blockIdx.x) * AQ;   // longest tiles first
    const int b = bh >> 4, h = bh & 15;
    const int nt = q0 / AKT + 2;

    // Q fragments: rows q0+16w+{g,g+8}, scaled by 1/8, split hi/lo. Resident.
    uint32_t qhi[8][4], qlo[8][4];
    {
        const float* qb = Q + ((size_t)bh * Tc + q0 + wid * 16) * HDc;
        #pragma unroll
        for (int kc = 0; kc < 8; kc++) {
            const int c0 = kc * 8 + tg;
            float v[4];
            v[0] = qb[(size_t)g * HDc + c0] * 0.125f;
            v[1] = qb[(size_t)(g + 8) * HDc + c0] * 0.125f;
            v[2] = qb[(size_t)g * HDc + c0 + 4] * 0.125f;
            v[3] = qb[(size_t)(g + 8) * HDc + c0 + 4] * 0.125f;
            #pragma unroll
            for (int r = 0; r < 4; r++) {
                const float hv = tf32r(v[r]);
                qhi[kc][r] = __float_as_uint(hv);
                qlo[kc][r] = __float_as_uint(tf32r(v[r] - hv));
            }
        }
    }

    auto load_stage = [&](int t_, int s_) {
        const uint32_t base = sb + (uint32_t)(s_ * ASTAGE_F) * 4;
        const int k0_ = t_ * AKT;
        const size_t kg = ((size_t)bh * Tc + k0_) * HDc;
        const size_t vg = (size_t)bh * HDc * Tc + k0_;
        #pragma unroll
        for (int i = 0; i < 4; i++) {
            const int u = i * 128 + tid;              // 0..511
            const int r = u >> 4, c = (u & 15) * 4;
            cp_async16(base + (uint32_t)(r * KSTr + c) * 4, Khi + kg + (size_t)r * HDc + c);
        }
        #pragma unroll
        for (int i = 0; i < 4; i++) {
            const int u = i * 128 + tid;
            const int r = u >> 4, c = (u & 15) * 4;
            cp_async16(base + (uint32_t)(KTILE_F + r * KSTr + c) * 4, Klo + kg + (size_t)r * HDc + c);
        }
        #pragma unroll
        for (int i = 0; i < 4; i++) {
            const int u = i * 128 + tid;
            const int r = u >> 3, c = (u & 7) * 4;
            cp_async16(base + (uint32_t)(2 * KTILE_F + r * VSTr + c) * 4,
                       Vthi + vg + (size_t)r * Tc + c);
        }
        #pragma unroll
        for (int i = 0; i < 4; i++) {
            const int u = i * 128 + tid;
            const int r = u >> 3, c = (u & 7) * 4;
            cp_async16(base + (uint32_t)(2 * KTILE_F + VTILE_F + r * VSTr + c) * 4,
                       Vtlo + vg + (size_t)r * Tc + c);
        }
        cp_commit();
    };

    float acc_o[8][4] = {};
    float m0 = -INFINITY, m1 = -INFINITY, l0 = 0.f, l1 = 0.f;
    const int row0 = q0 + wid * 16 + g;

    load_stage(0, 0);
    if (nt > 1) load_stage(1, 1); else cp_commit();

    for (int t = 0; t < nt; t++) {
        const int s = t & 1;
        const int k0 = t * AKT;
        cp_wait<1>();
        __syncthreads();

        const float* Ks_hi = as_ + s * ASTAGE_F;
        const float* Ks_lo = Ks_hi + KTILE_F;
        const float* Vs_hi = Ks_hi + 2 * KTILE_F;
        const float* Vs_lo = Vs_hi + VTILE_F;
        float* Pw = as_ + P_OFF + wid * (16 * 36);

        // ---- S = Q @ K^T (3xTF32) ----
        float sacc[4][4] = {};
        #pragma unroll
        for (int kc = 0; kc < 8; kc++) {
            #pragma unroll
            for (int n_ = 0; n_ < 4; n_++) {
                const int bi = (n_ * 8 + g) * KSTr + kc * 8 + tg;
                uint32_t kh[2], kl[2];
                kh[0] = __float_as_uint(Ks_hi[bi]);
                kh[1] = __float_as_uint(Ks_hi[bi + 4]);
                kl[0] = __float_as_uint(Ks_lo[bi]);
                kl[1] = __float_as_uint(Ks_lo[bi + 4]);
                mma_tf32(sacc[n_], qlo[kc], kh);
                mma_tf32(sacc[n_], qhi[kc], kl);
                mma_tf32(sacc[n_], qhi[kc], kh);
            }
        }

        // ---- causal mask ----
        if (k0 + AKT - 1 > q0 + wid * 16) {
            #pragma unroll
            for (int n_ = 0; n_ < 4; n_++) {
                const int c0 = k0 + n_ * 8 + 2 * tg;
                if (c0 > row0)     sacc[n_][0] = -1e30f;
                if (c0 + 1 > row0) sacc[n_][1] = -1e30f;
                if (c0 > row0 + 8)     sacc[n_][2] = -1e30f;
                if (c0 + 1 > row0 + 8) sacc[n_][3] = -1e30f;
            }
        }

        // ---- online softmax ----
        float tx0 = sacc[0][0], tx1 = sacc[0][2];
        #pragma unroll
        for (int n_ = 0; n_ < 4; n_++) {
            tx0 = fmaxf(tx0, fmaxf(sacc[n_][0], sacc[n_][1]));
            tx1 = fmaxf(tx1, fmaxf(sacc[n_][2], sacc[n_][3]));
        }
        tx0 = fmaxf(tx0, __shfl_xor_sync(0xffffffffu, tx0, 1));
        tx0 = fmaxf(tx0, __shfl_xor_sync(0xffffffffu, tx0, 2));
        tx1 = fmaxf(tx1, __shfl_xor_sync(0xffffffffu, tx1, 1));
        tx1 = fmaxf(tx1, __shfl_xor_sync(0xffffffffu, tx1, 2));
        const float mn0 = fmaxf(m0, tx0), mn1 = fmaxf(m1, tx1);
        const float c0f = __expf(m0 - mn0), c1f = __expf(m1 - mn1);
        m0 = mn0; m1 = mn1;

        float rs0 = 0.f, rs1 = 0.f;
        #pragma unroll
        for (int n_ = 0; n_ < 4; n_++) {
            const float p0 = __expf(sacc[n_][0] - mn0);
            const float p1 = __expf(sacc[n_][1] - mn0);
            const float p2 = __expf(sacc[n_][2] - mn1);
            const float p3 = __expf(sacc[n_][3] - mn1);
            rs0 += p0 + p1; rs1 += p2 + p3;
            float2 w0; w0.x = p0; w0.y = p1;
            float2 w1; w1.x = p2; w1.y = p3;
            *(float2*)&Pw[g * 36 + n_ * 8 + 2 * tg] = w0;
            *(float2*)&Pw[(g + 8) * 36 + n_ * 8 + 2 * tg] = w1;
        }
        rs0 += __shfl_xor_sync(0xffffffffu, rs0, 1);
        rs0 += __shfl_xor_sync(0xffffffffu, rs0, 2);
        rs1 += __shfl_xor_sync(0xffffffffu, rs1, 1);
        rs1 += __shfl_xor_sync(0xffffffffu, rs1, 2);
        l0 = l0 * c0f + rs0;
        l1 = l1 * c1f + rs1;

        #pragma unroll
        for (int d8 = 0; d8 < 8; d8++) {
            acc_o[d8][0] *= c0f; acc_o[d8][1] *= c0f;
            acc_o[d8][2] *= c1f; acc_o[d8][3] *= c1f;
        }
        __syncwarp();

        // ---- O += P @ V (3xTF32) ----
        #pragma unroll
        for (int kc = 0; kc < 4; kc++) {
            float pv[4];
            pv[0] = Pw[g * 36 + kc * 8 + tg];
            pv[1] = Pw[(g + 8) * 36 + kc * 8 + tg];
            pv[2] = Pw[g * 36 + kc * 8 + tg + 4];
            pv[3] = Pw[(g + 8) * 36 + kc * 8 + tg + 4];
            uint32_t ah[4], al[4];
            #pragma unroll
            for (int r = 0; r < 4; r++) {
                const float hv = tf32r(pv[r]);
                ah[r] = __float_as_uint(hv);
                al[r] = __float_as_uint(tf32r(pv[r] - hv));
            }
            #pragma unroll
            for (int d8 = 0; d8 < 8; d8++) {
                const int bi = (d8 * 8 + g) * VSTr + kc * 8 + tg;
                uint32_t vh[2], vl[2];
                vh[0] = __float_as_uint(Vs_hi[bi]);
                vh[1] = __float_as_uint(Vs_hi[bi + 4]);
                vl[0] = __float_as_uint(Vs_lo[bi]);
                vl[1] = __float_as_uint(Vs_lo[bi + 4]);
                mma_tf32(acc_o[d8], al, vh);
                mma_tf32(acc_o[d8], ah, vl);
                mma_tf32(acc_o[d8], ah, vh);
            }
        }
        __syncwarp();

        __syncthreads();
        if (t + 2 < nt) load_stage(t + 2, s); else cp_commit();
    }

    // ---- epilogue: O/l, split hi/lo, merge heads into [B*T, D] ----
    const float il0 = 1.f / l0, il1 = 1.f / l1;
    const size_t ob0 = ((size_t)b * Tc + row0) * Dc + (size_t)h * HDc;
    const size_t ob1 = ob0 + (size_t)8 * Dc;
    #pragma unroll
    for (int d8 = 0; d8 < 8; d8++) {
        const int c = d8 * 8 + 2 * tg;
        float v0 = acc_o[d8][0] * il0, v1 = acc_o[d8][1] * il0;
        float v2 = acc_o[d8][2] * il1, v3 = acc_o[d8][3] * il1;
        float2 h0, l0v, h1, l1v;
        h0.x = tf32r(v0); l0v.x = tf32r(v0 - h0.x);
        h0.y = tf32r(v1); l0v.y = tf32r(v1 - h0.y);
        h1.x = tf32r(v2); l1v.x = tf32r(v2 - h1.x);
        h1.y = tf32r(v3); l1v.y = tf32r(v3 - h1.y);
        *(float2*)&Ohi[ob0 + c] = h0;
        *(float2*)&Olo[ob0 + c] = l0v;
        *(float2*)&Ohi[ob1 + c] = h1;
        *(float2*)&Olo[ob1 + c] = l1v;
    }
}

// ---------------------------------------------------------------------------
// Launch
// ---------------------------------------------------------------------------
extern "C" void kernel_launch(void* const* d_in, const int* in_sizes, int n_in,
                              void* d_out, int out_size)
{
    const float* x  = (const float*)d_in[0];
    const float* Wq = (const float*)d_in[1];
    const float* bq = (const float*)d_in[2];
    const float* Wk = (const float*)d_in[3];
    const float* bk = (const float*)d_in[4];
    const float* Wv = (const float*)d_in[5];
    const float* bv = (const float*)d_in[6];
    const float* Wo = (const float*)d_in[7];
    const float* bo = (const float*)d_in[8];
    float* out = (float*)d_out;

    float *Xhi, *Xlo, *Qp, *Kp, *Vp, *Khi, *Klo, *Vthi, *Vtlo, *Ahi, *Alo, *Whi, *Wlo;
    cudaGetSymbolAddress((void**)&Xhi, g_Xhi);
    cudaGetSymbolAddress((void**)&Xlo, g_Xlo);
    cudaGetSymbolAddress((void**)&Qp, g_Q);
    cudaGetSymbolAddress((void**)&Kp, g_K);
    cudaGetSymbolAddress((void**)&Vp, g_V);
    cudaGetSymbolAddress((void**)&Khi, g_Khi);
    cudaGetSymbolAddress((void**)&Klo, g_Klo);
    cudaGetSymbolAddress((void**)&Vthi, g_Vthi);
    cudaGetSymbolAddress((void**)&Vtlo, g_Vtlo);
    cudaGetSymbolAddress((void**)&Ahi, g_Ahi);
    cudaGetSymbolAddress((void**)&Alo, g_Alo);
    cudaGetSymbolAddress((void**)&Whi, g_Wthi);
    cudaGetSymbolAddress((void**)&Wlo, g_Wtlo);

    cudaFuncSetAttribute(gemm_3xtf32<true>,  cudaFuncAttributeMaxDynamicSharedMemorySize, GEMM_SMEM);
    cudaFuncSetAttribute(gemm_3xtf32<false>, cudaFuncAttributeMaxDynamicSharedMemorySize, GEMM_SMEM);
    cudaFuncSetAttribute(attn_mma, cudaFuncAttributeMaxDynamicSharedMemorySize, ATTN_SMEM);

    // 1) prep: split X; transpose+split weights
    const int n4 = Mc * Dc / 4;
    split_tf32_kernel<<<(n4 + 255) / 256, 256>>>(x, Xhi, Xlo, n4);
    transpose4_split<<<dim3(32, 32, 4), dim3(32, 8)>>>(Wq, Wk, Wv, Wo, Whi, Wlo);

    // 2) Q/K/V projections (3xTF32 tensor cores)
    const dim3 gg(Dc / BN, Mc / BM);
    const size_t DD = (size_t)Dc * Dc;
    gemm_3xtf32<true><<<gg, 256, GEMM_SMEM>>>(Xhi, Xlo, Whi + 0 * DD, Wlo + 0 * DD, bq, Qp);
    gemm_3xtf32<true><<<gg, 256, GEMM_SMEM>>>(Xhi, Xlo, Whi + 1 * DD, Wlo + 1 * DD, bk, Kp);
    gemm_3xtf32<true><<<gg, 256, GEMM_SMEM>>>(Xhi, Xlo, Whi + 2 * DD, Wlo + 2 * DD, bv, Vp);

    // 3) prep K (hi/lo split) and V (transpose + split) for mma attention
    split_tf32_kernel<<<(n4 + 255) / 256, 256>>>(Kp, Khi, Klo, n4);
    trans_split_V<<<dim3(Tc / 32, HDc / 32, Bc * Hc), dim3(32, 8)>>>(Vp, Vthi, Vtlo);

    // 4) attention (tensor cores, 3xTF32)
    const dim3 ag(Tc / AQ, Bc * Hc);   // (32, 32)
    attn_mma<<<ag, 128, ATTN_SMEM>>>(Qp, Khi, Klo, Vthi, Vtlo, Ahi, Alo);

    // 5) output projection -> d_out
    gemm_3xtf32<false><<<gg, 256, GEMM_SMEM>>>(Ahi, Alo, Whi + 3 * DD, Wlo + 3 * DD, bo, out);
}

// round 7
// speedup vs baseline: 3.2037x; 1.0082x over previous
#include <cuda_runtime.h>
#include <cuda_bf16.h>
#include <math.h>
#include <stdint.h>

// Problem constants
constexpr int Bc  = 2;
constexpr int Tc  = 2048;
constexpr int Dc  = 1024;
constexpr int Hc  = 16;
constexpr int HDc = 64;
constexpr int Mc  = Bc * Tc;      // 4096

// ---------------------------------------------------------------------------
// Scratch (device globals; no allocations allowed)
// ---------------------------------------------------------------------------
__device__ float g_Xhi[Mc * Dc];
__device__ float g_Xlo[Mc * Dc];
__device__ float g_Q[Bc * Hc * Tc * HDc];
__device__ float g_V[Bc * Hc * Tc * HDc];
__device__ float g_Khi[Bc * Hc * Tc * HDc];
__device__ float g_Klo[Bc * Hc * Tc * HDc];
__device__ float g_Vthi[Bc * Hc * Tc * HDc];   // transposed: [bh][d][t]
__device__ float g_Vtlo[Bc * Hc * Tc * HDc];
__device__ float g_Ahi[Bc * Tc * Dc];
__device__ float g_Alo[Bc * Tc * Dc];
__device__ float g_Wthi[4 * Dc * Dc];
__device__ float g_Wtlo[4 * Dc * Dc];

// ---------------------------------------------------------------------------
// Helpers
// ---------------------------------------------------------------------------
__device__ __forceinline__ float tf32r(float x) {
    uint32_t r;
    asm("cvt.rna.tf32.f32 %0, %1;" : "=r"(r) : "f"(x));
    return __uint_as_float(r);
}

__device__ __forceinline__ uint32_t smem_to_u32(const void* p) {
    uint32_t a;
    asm("{ .reg .u64 t; cvta.to.shared.u64 t, %1; cvt.u32.u64 %0, t; }" : "=r"(a) : "l"(p));
    return a;
}

__device__ __forceinline__ void cp_async16(uint32_t saddr, const void* gaddr) {
    asm volatile("cp.async.cg.shared.global [%0], [%1], 16;" :: "r"(saddr), "l"(gaddr));
}
__device__ __forceinline__ void cp_commit() {
    asm volatile("cp.async.commit_group;" ::: "memory");
}
template <int N>
__device__ __forceinline__ void cp_wait() {
    asm volatile("cp.async.wait_group %0;" :: "n"(N) : "memory");
}

// tf32 m16n8k8 mma.sync
__device__ __forceinline__ void mma_tf32(float* d, const uint32_t* a, const uint32_t* b) {
    asm volatile(
        "mma.sync.aligned.m16n8k8.row.col.f32.tf32.tf32.f32 "
        "{%0,%1,%2,%3}, {%4,%5,%6,%7}, {%8,%9}, {%0,%1,%2,%3};"
        : "+f"(d[0]), "+f"(d[1]), "+f"(d[2]), "+f"(d[3])
        : "r"(a[0]), "r"(a[1]), "r"(a[2]), "r"(a[3]), "r"(b[0]), "r"(b[1]));
}

// ---------------------------------------------------------------------------
// Prep: split float array into tf32 hi/lo (float4 per thread)
// ---------------------------------------------------------------------------
__global__ __launch_bounds__(256)
void split_tf32_kernel(const float* __restrict__ in, float* __restrict__ hi,
                       float* __restrict__ lo, int n4)
{
    int i = blockIdx.x * 256 + threadIdx.x;
    if (i < n4) {
        float4 v = ((const float4*)in)[i];
        float4 h, l;
        h.x = tf32r(v.x); l.x = tf32r(v.x - h.x);
        h.y = tf32r(v.y); l.y = tf32r(v.y - h.y);
        h.z = tf32r(v.z); l.z = tf32r(v.z - h.z);
        h.w = tf32r(v.w); l.w = tf32r(v.w - h.w);
        ((float4*)hi)[i] = h;
        ((float4*)lo)[i] = l;
    }
}

// ---------------------------------------------------------------------------
// Prep: per-head transpose + split of V: Vt[bh][d][t] = split(V[bh][t][d])
// ---------------------------------------------------------------------------
__global__ __launch_bounds__(256)
void trans_split_V(const float* __restrict__ V, float* __restrict__ Thi,
                   float* __restrict__ Tlo)
{
    __shared__ float tile[32][33];
    const int bh = blockIdx.z;
    const int t0 = blockIdx.x * 32, d0 = blockIdx.y * 32;
    const int tx = threadIdx.x, ty = threadIdx.y;
    const float* src = V + (size_t)bh * Tc * HDc;
    #pragma unroll
    for (int j = 0; j < 32; j += 8)
        tile[ty + j][tx] = src[(size_t)(t0 + ty + j) * HDc + d0 + tx];
    __syncthreads();
    float* dh = Thi + (size_t)bh * HDc * Tc;
    float* dl = Tlo + (size_t)bh * HDc * Tc;
    #pragma unroll
    for (int j = 0; j < 32; j += 8) {
        const float v = tile[tx][ty + j];
        const float h = tf32r(v);
        dh[(size_t)(d0 + ty + j) * Tc + t0 + tx] = h;
        dl[(size_t)(d0 + ty + j) * Tc + t0 + tx] = tf32r(v - h);
    }
}

// ---------------------------------------------------------------------------
// Weight transpose + split: Wt_{hi,lo}[n][k] = split(W[k][n])  (4 matrices)
// ---------------------------------------------------------------------------
__global__ __launch_bounds__(256)
void transpose4_split(const float* __restrict__ W0, const float* __restrict__ W1,
                      const float* __restrict__ W2, const float* __restrict__ W3,
                      float* __restrict__ Thi, float* __restrict__ Tlo)
{
    __shared__ float tile[32][33];
    const int z = blockIdx.z;
    const float* W = (z == 0) ? W0 : (z == 1) ? W1 : (z == 2) ? W2 : W3;
    const size_t zoff = (size_t)z * Dc * Dc;

    const int tx = threadIdx.x, ty = threadIdx.y;
    int x = blockIdx.x * 32 + tx;
    int y = blockIdx.y * 32 + ty;
    #pragma unroll
    for (int j = 0; j < 32; j += 8)
        tile[ty + j][tx] = W[(size_t)(y + j) * Dc + x];
    __syncthreads();
    x = blockIdx.y * 32 + tx;
    y = blockIdx.x * 32 + ty;
    #pragma unroll
    for (int j = 0; j < 32; j += 8) {
        const float v = tile[tx][ty + j];
        const float h = tf32r(v);
        Thi[zoff + (size_t)(y + j) * Dc + x] = h;
        Tlo[zoff + (size_t)(y + j) * Dc + x] = tf32r(v - h);
    }
}

// ---------------------------------------------------------------------------
// 3xTF32 mma.sync GEMM:  Y = X @ Wt^T + bias
// CTA tile 128x128, BK=32, THREE-stage cp.async pipeline, 8 warps, warp 64x32.
// MODE: 0 = flat [M,D] output; 1 = head-split output; 2 = head-split + hi/lo split
// ---------------------------------------------------------------------------
constexpr int BM = 128, BN = 128, BKC = 32;
constexpr int NCH = Dc / BKC;            // 32
constexpr int SST = BKC + 4;             // 36
constexpr int TILE_F = BM * SST;         // 4608
constexpr int STAGE_F = 4 * TILE_F;      // Ahi, Alo, Bhi, Blo
constexpr int NSTG = 3;
constexpr int GEMM_SMEM = NSTG * STAGE_F * 4;   // 221184 B

template <int MODE>
__global__ __launch_bounds__(256, 1)
void gemm_3xtf32(const float* __restrict__ Xhi, const float* __restrict__ Xlo,
                 const float* __restrict__ Whi, const float* __restrict__ Wlo,
                 const float* __restrict__ bias,
                 float* __restrict__ Y, float* __restrict__ Y2)
{
    extern __shared__ __align__(16) float smem[];
    const uint32_t sb = smem_to_u32(smem);
    const int tid = threadIdx.x;
    const int wid = tid >> 5, lane = tid & 31;
    const int g = lane >> 2, tg = lane & 3;
    const int wm = wid & 1;
    const int wn = wid >> 1;
    const int m0 = blockIdx.y * BM;
    const int n0 = blockIdx.x * BN;

    auto load_chunk = [&](int k, int s) {
        const uint32_t sbase = sb + (uint32_t)s * STAGE_F * 4;
        const size_t aoff = (size_t)m0 * Dc + k * BKC;
        const size_t boff = (size_t)n0 * Dc + k * BKC;
        const float* srcs[4] = {Xhi + aoff, Xlo + aoff, Whi + boff, Wlo + boff};
        #pragma unroll
        for (int t = 0; t < 4; t++) {
            const float* gsrc = srcs[t];
            const uint32_t tbase = sbase + (uint32_t)t * TILE_F * 4;
            #pragma unroll
            for (int i = 0; i < 4; i++) {
                const int u = i * 256 + tid;
                const int row = u >> 3, kc = (u & 7) << 2;
                cp_async16(tbase + (uint32_t)(row * SST + kc) * 4,
                           gsrc + (size_t)row * Dc + kc);
            }
        }
        cp_commit();
    };

    float acc[4][4][4] = {};

    load_chunk(0, 0);
    load_chunk(1, 1);
    load_chunk(2, 2);

    int s = 0;
    for (int k = 0; k < NCH; k++) {
        cp_wait<2>();
        __syncthreads();

        const float* Ahi = smem + s * STAGE_F;
        const float* Alo = Ahi + TILE_F;
        const float* Bhi = Alo + TILE_F;
        const float* Blo = Bhi + TILE_F;

        #pragma unroll
        for (int kk = 0; kk < 4; kk++) {
            const int kb = kk * 8;
            uint32_t ah[4][4], al[4][4], bh[4][2], bl[4][2];
            #pragma unroll
            for (int mi = 0; mi < 4; mi++) {
                const int r = wm * 64 + mi * 16;
                const int i00 = (r + g) * SST + kb + tg;
                const int i10 = (r + g + 8) * SST + kb + tg;
                ah[mi][0] = __float_as_uint(Ahi[i00]);
                ah[mi][1] = __float_as_uint(Ahi[i10]);
                ah[mi][2] = __float_as_uint(Ahi[i00 + 4]);
                ah[mi][3] = __float_as_uint(Ahi[i10 + 4]);
                al[mi][0] = __float_as_uint(Alo[i00]);
                al[mi][1] = __float_as_uint(Alo[i10]);
                al[mi][2] = __float_as_uint(Alo[i00 + 4]);
                al[mi][3] = __float_as_uint(Alo[i10 + 4]);
            }
            #pragma unroll
            for (int ni = 0; ni < 4; ni++) {
                const int r = wn * 32 + ni * 8;
                const int i0 = (r + g) * SST + kb + tg;
                bh[ni][0] = __float_as_uint(Bhi[i0]);
                bh[ni][1] = __float_as_uint(Bhi[i0 + 4]);
                bl[ni][0] = __float_as_uint(Blo[i0]);
                bl[ni][1] = __float_as_uint(Blo[i0 + 4]);
            }
            #pragma unroll
            for (int mi = 0; mi < 4; mi++)
                #pragma unroll
                for (int ni = 0; ni < 4; ni++) {
                    mma_tf32(acc[mi][ni], al[mi], bh[ni]);
                    mma_tf32(acc[mi][ni], ah[mi], bl[ni]);
                    mma_tf32(acc[mi][ni], ah[mi], bh[ni]);
                }
        }

        __syncthreads();
        if (k + NSTG < NCH) load_chunk(k + NSTG, s); else cp_commit();
        s = (s == NSTG - 1) ? 0 : s + 1;
    }

    #pragma unroll
    for (int mi = 0; mi < 4; mi++) {
        const int row0 = m0 + wm * 64 + mi * 16 + g;
        #pragma unroll
        for (int ni = 0; ni < 4; ni++) {
            const int col = n0 + wn * 32 + ni * 8 + 2 * tg;
            const float2 bv = *(const float2*)&bias[col];
            float2 v0, v1;
            v0.x = acc[mi][ni][0] + bv.x;  v0.y = acc[mi][ni][1] + bv.y;
            v1.x = acc[mi][ni][2] + bv.x;  v1.y = acc[mi][ni][3] + bv.y;
            if (MODE == 0) {
                *(float2*)(Y + (size_t)row0 * Dc + col) = v0;
                *(float2*)(Y + (size_t)(row0 + 8) * Dc + col) = v1;
            } else {
                const int h = col >> 6, d0 = col & 63;
                const int b0i = row0 >> 11, t0 = row0 & 2047;
                const size_t p0 = ((((size_t)b0i * Hc + h) * Tc + t0) << 6) + d0;
                const int row1 = row0 + 8;
                const int b1i = row1 >> 11, t1 = row1 & 2047;
                const size_t p1 = ((((size_t)b1i * Hc + h) * Tc + t1) << 6) + d0;
                if (MODE == 1) {
                    *(float2*)(Y + p0) = v0;
                    *(float2*)(Y + p1) = v1;
                } else {
                    float2 h0, l0, h1, l1;
                    h0.x = tf32r(v0.x); l0.x = tf32r(v0.x - h0.x);
                    h0.y = tf32r(v0.y); l0.y = tf32r(v0.y - h0.y);
                    h1.x = tf32r(v1.x); l1.x = tf32r(v1.x - h1.x);
                    h1.y = tf32r(v1.y); l1.y = tf32r(v1.y - h1.y);
                    *(float2*)(Y  + p0) = h0;
                    *(float2*)(Y2 + p0) = l0;
                    *(float2*)(Y  + p1) = h1;
                    *(float2*)(Y2 + p1) = l1;
                }
            }
        }
    }
}

// ---------------------------------------------------------------------------
// mma.sync flash attention (3xTF32 for QK^T and PV), causal. (R6-proven)
// ---------------------------------------------------------------------------
constexpr int AQ  = 64;
constexpr int AKT = 32;
constexpr int KSTr = 68;
constexpr int VSTr = 36;
constexpr int KTILE_F = AKT * KSTr;      // 2176
constexpr int VTILE_F = HDc * VSTr;      // 2304
constexpr int ASTAGE_F = 2 * KTILE_F + 2 * VTILE_F;  // 8960
constexpr int P_OFF = 2 * ASTAGE_F;
constexpr int ATTN_SMEM = (P_OFF + 4 * 16 * 36) * 4; // 80896 B

__global__ __launch_bounds__(128, 1)
void attn_mma(const float* __restrict__ Q,
              const float* __restrict__ Khi, const float* __restrict__ Klo,
              const float* __restrict__ Vthi, const float* __restrict__ Vtlo,
              float* __restrict__ Ohi, float* __restrict__ Olo)
{
    extern __shared__ __align__(16) float as_[];
    const uint32_t sb = smem_to_u32(as_);
    const int tid = threadIdx.x, wid = tid >> 5, lane = tid & 31;
    const int g = lane >> 2, tg = lane & 3;
    const int bh = blockIdx.y;
    const int q0 = (int)(gridDim.x - 1 - blockIdx.x) * AQ;   // longest tiles first
    const int b = bh >> 4, h = bh & 15;
    const int nt = q0 / AKT + 2;

    uint32_t qhi[8][4], qlo[8][4];
    {
        const float* qb = Q + ((size_t)bh * Tc + q0 + wid * 16) * HDc;
        #pragma unroll
        for (int kc = 0; kc < 8; kc++) {
            const int c0 = kc * 8 + tg;
            float v[4];
            v[0] = qb[(size_t)g * HDc + c0] * 0.125f;
            v[1] = qb[(size_t)(g + 8) * HDc + c0] * 0.125f;
            v[2] = qb[(size_t)g * HDc + c0 + 4] * 0.125f;
            v[3] = qb[(size_t)(g + 8) * HDc + c0 + 4] * 0.125f;
            #pragma unroll
            for (int r = 0; r < 4; r++) {
                const float hv = tf32r(v[r]);
                qhi[kc][r] = __float_as_uint(hv);
                qlo[kc][r] = __float_as_uint(tf32r(v[r] - hv));
            }
        }
    }

    auto load_stage = [&](int t_, int s_) {
        const uint32_t base = sb + (uint32_t)(s_ * ASTAGE_F) * 4;
        const int k0_ = t_ * AKT;
        const size_t kg = ((size_t)bh * Tc + k0_) * HDc;
        const size_t vg = (size_t)bh * HDc * Tc + k0_;
        #pragma unroll
        for (int i = 0; i < 4; i++) {
            const int u = i * 128 + tid;
            const int r = u >> 4, c = (u & 15) * 4;
            cp_async16(base + (uint32_t)(r * KSTr + c) * 4, Khi + kg + (size_t)r * HDc + c);
        }
        #pragma unroll
        for (int i = 0; i < 4; i++) {
            const int u = i * 128 + tid;
            const int r = u >> 4, c = (u & 15) * 4;
            cp_async16(base + (uint32_t)(KTILE_F + r * KSTr + c) * 4, Klo + kg + (size_t)r * HDc + c);
        }
        #pragma unroll
        for (int i = 0; i < 4; i++) {
            const int u = i * 128 + tid;
            const int r = u >> 3, c = (u & 7) * 4;
            cp_async16(base + (uint32_t)(2 * KTILE_F + r * VSTr + c) * 4,
                       Vthi + vg + (size_t)r * Tc + c);
        }
        #pragma unroll
        for (int i = 0; i < 4; i++) {
            const int u = i * 128 + tid;
            const int r = u >> 3, c = (u & 7) * 4;
            cp_async16(base + (uint32_t)(2 * KTILE_F + VTILE_F + r * VSTr + c) * 4,
                       Vtlo + vg + (size_t)r * Tc + c);
        }
        cp_commit();
    };

    float acc_o[8][4] = {};
    float m0 = -INFINITY, m1 = -INFINITY, l0 = 0.f, l1 = 0.f;
    const int row0 = q0 + wid * 16 + g;

    load_stage(0, 0);
    if (nt > 1) load_stage(1, 1); else cp_commit();

    for (int t = 0; t < nt; t++) {
        const int s = t & 1;
        const int k0 = t * AKT;
        cp_wait<1>();
        __syncthreads();

        const float* Ks_hi = as_ + s * ASTAGE_F;
        const float* Ks_lo = Ks_hi + KTILE_F;
        const float* Vs_hi = Ks_hi + 2 * KTILE_F;
        const float* Vs_lo = Vs_hi + VTILE_F;
        float* Pw = as_ + P_OFF + wid * (16 * 36);

        // ---- S = Q @ K^T (3xTF32) ----
        float sacc[4][4] = {};
        #pragma unroll
        for (int kc = 0; kc < 8; kc++) {
            #pragma unroll
            for (int n_ = 0; n_ < 4; n_++) {
                const int bi = (n_ * 8 + g) * KSTr + kc * 8 + tg;
                uint32_t kh[2], kl[2];
                kh[0] = __float_as_uint(Ks_hi[bi]);
                kh[1] = __float_as_uint(Ks_hi[bi + 4]);
                kl[0] = __float_as_uint(Ks_lo[bi]);
                kl[1] = __float_as_uint(Ks_lo[bi + 4]);
                mma_tf32(sacc[n_], qlo[kc], kh);
                mma_tf32(sacc[n_], qhi[kc], kl);
                mma_tf32(sacc[n_], qhi[kc], kh);
            }
        }

        // ---- causal mask ----
        if (k0 + AKT - 1 > q0 + wid * 16) {
            #pragma unroll
            for (int n_ = 0; n_ < 4; n_++) {
                const int c0 = k0 + n_ * 8 + 2 * tg;
                if (c0 > row0)     sacc[n_][0] = -1e30f;
                if (c0 + 1 > row0) sacc[n_][1] = -1e30f;
                if (c0 > row0 + 8)     sacc[n_][2] = -1e30f;
                if (c0 + 1 > row0 + 8) sacc[n_][3] = -1e30f;
            }
        }

        // ---- online softmax ----
        float tx0 = sacc[0][0], tx1 = sacc[0][2];
        #pragma unroll
        for (int n_ = 0; n_ < 4; n_++) {
            tx0 = fmaxf(tx0, fmaxf(sacc[n_][0], sacc[n_][1]));
            tx1 = fmaxf(tx1, fmaxf(sacc[n_][2], sacc[n_][3]));
        }
        tx0 = fmaxf(tx0, __shfl_xor_sync(0xffffffffu, tx0, 1));
        tx0 = fmaxf(tx0, __shfl_xor_sync(0xffffffffu, tx0, 2));
        tx1 = fmaxf(tx1, __shfl_xor_sync(0xffffffffu, tx1, 1));
        tx1 = fmaxf(tx1, __shfl_xor_sync(0xffffffffu, tx1, 2));
        const float mn0 = fmaxf(m0, tx0), mn1 = fmaxf(m1, tx1);
        const float c0f = __expf(m0 - mn0), c1f = __expf(m1 - mn1);
        m0 = mn0; m1 = mn1;

        float rs0 = 0.f, rs1 = 0.f;
        #pragma unroll
        for (int n_ = 0; n_ < 4; n_++) {
            const float p0 = __expf(sacc[n_][0] - mn0);
            const float p1 = __expf(sacc[n_][1] - mn0);
            const float p2 = __expf(sacc[n_][2] - mn1);
            const float p3 = __expf(sacc[n_][3] - mn1);
            rs0 += p0 + p1; rs1 += p2 + p3;
            float2 w0; w0.x = p0; w0.y = p1;
            float2 w1; w1.x = p2; w1.y = p3;
            *(float2*)&Pw[g * 36 + n_ * 8 + 2 * tg] = w0;
            *(float2*)&Pw[(g + 8) * 36 + n_ * 8 + 2 * tg] = w1;
        }
        rs0 += __shfl_xor_sync(0xffffffffu, rs0, 1);
        rs0 += __shfl_xor_sync(0xffffffffu, rs0, 2);
        rs1 += __shfl_xor_sync(0xffffffffu, rs1, 1);
        rs1 += __shfl_xor_sync(0xffffffffu, rs1, 2);
        l0 = l0 * c0f + rs0;
        l1 = l1 * c1f + rs1;

        #pragma unroll
        for (int d8 = 0; d8 < 8; d8++) {
            acc_o[d8][0] *= c0f; acc_o[d8][1] *= c0f;
            acc_o[d8][2] *= c1f; acc_o[d8][3] *= c1f;
        }
        __syncwarp();

        // ---- O += P @ V (3xTF32) ----
        #pragma unroll
        for (int kc = 0; kc < 4; kc++) {
            float pv[4];
            pv[0] = Pw[g * 36 + kc * 8 + tg];
            pv[1] = Pw[(g + 8) * 36 + kc * 8 + tg];
            pv[2] = Pw[g * 36 + kc * 8 + tg + 4];
            pv[3] = Pw[(g + 8) * 36 + kc * 8 + tg + 4];
            uint32_t ah[4], al[4];
            #pragma unroll
            for (int r = 0; r < 4; r++) {
                const float hv = tf32r(pv[r]);
                ah[r] = __float_as_uint(hv);
                al[r] = __float_as_uint(tf32r(pv[r] - hv));
            }
            #pragma unroll
            for (int d8 = 0; d8 < 8; d8++) {
                const int bi = (d8 * 8 + g) * VSTr + kc * 8 + tg;
                uint32_t vh[2], vl[2];
                vh[0] = __float_as_uint(Vs_hi[bi]);
                vh[1] = __float_as_uint(Vs_hi[bi + 4]);
                vl[0] = __float_as_uint(Vs_lo[bi]);
                vl[1] = __float_as_uint(Vs_lo[bi + 4]);
                mma_tf32(acc_o[d8], al, vh);
                mma_tf32(acc_o[d8], ah, vl);
                mma_tf32(acc_o[d8], ah, vh);
            }
        }
        __syncwarp();

        __syncthreads();
        if (t + 2 < nt) load_stage(t + 2, s); else cp_commit();
    }

    // ---- epilogue ----
    const float il0 = 1.f / l0, il1 = 1.f / l1;
    const size_t ob0 = ((size_t)b * Tc + row0) * Dc + (size_t)h * HDc;
    const size_t ob1 = ob0 + (size_t)8 * Dc;
    #pragma unroll
    for (int d8 = 0; d8 < 8; d8++) {
        const int c = d8 * 8 + 2 * tg;
        float v0 = acc_o[d8][0] * il0, v1 = acc_o[d8][1] * il0;
        float v2 = acc_o[d8][2] * il1, v3 = acc_o[d8][3] * il1;
        float2 h0, l0v, h1, l1v;
        h0.x = tf32r(v0); l0v.x = tf32r(v0 - h0.x);
        h0.y = tf32r(v1); l0v.y = tf32r(v1 - h0.y);
        h1.x = tf32r(v2); l1v.x = tf32r(v2 - h1.x);
        h1.y = tf32r(v3); l1v.y = tf32r(v3 - h1.y);
        *(float2*)&Ohi[ob0 + c] = h0;
        *(float2*)&Olo[ob0 + c] = l0v;
        *(float2*)&Ohi[ob1 + c] = h1;
        *(float2*)&Olo[ob1 + c] = l1v;
    }
}

// ---------------------------------------------------------------------------
// Launch
// ---------------------------------------------------------------------------
extern "C" void kernel_launch(void* const* d_in, const int* in_sizes, int n_in,
                              void* d_out, int out_size)
{
    const float* x  = (const float*)d_in[0];
    const float* Wq = (const float*)d_in[1];
    const float* bq = (const float*)d_in[2];
    const float* Wk = (const float*)d_in[3];
    const float* bk = (const float*)d_in[4];
    const float* Wv = (const float*)d_in[5];
    const float* bv = (const float*)d_in[6];
    const float* Wo = (const float*)d_in[7];
    const float* bo = (const float*)d_in[8];
    float* out = (float*)d_out;

    float *Xhi, *Xlo, *Qp, *Vp, *Khi, *Klo, *Vthi, *Vtlo, *Ahi, *Alo, *Whi, *Wlo;
    cudaGetSymbolAddress((void**)&Xhi, g_Xhi);
    cudaGetSymbolAddress((void**)&Xlo, g_Xlo);
    cudaGetSymbolAddress((void**)&Qp, g_Q);
    cudaGetSymbolAddress((void**)&Vp, g_V);
    cudaGetSymbolAddress((void**)&Khi, g_Khi);
    cudaGetSymbolAddress((void**)&Klo, g_Klo);
    cudaGetSymbolAddress((void**)&Vthi, g_Vthi);
    cudaGetSymbolAddress((void**)&Vtlo, g_Vtlo);
    cudaGetSymbolAddress((void**)&Ahi, g_Ahi);
    cudaGetSymbolAddress((void**)&Alo, g_Alo);
    cudaGetSymbolAddress((void**)&Whi, g_Wthi);
    cudaGetSymbolAddress((void**)&Wlo, g_Wtlo);

    cudaFuncSetAttribute(gemm_3xtf32<0>, cudaFuncAttributeMaxDynamicSharedMemorySize, GEMM_SMEM);
    cudaFuncSetAttribute(gemm_3xtf32<1>, cudaFuncAttributeMaxDynamicSharedMemorySize, GEMM_SMEM);
    cudaFuncSetAttribute(gemm_3xtf32<2>, cudaFuncAttributeMaxDynamicSharedMemorySize, GEMM_SMEM);
    cudaFuncSetAttribute(attn_mma, cudaFuncAttributeMaxDynamicSharedMemorySize, ATTN_SMEM);

    // 1) prep: split X; transpose+split weights
    const int n4 = Mc * Dc / 4;
    split_tf32_kernel<<<(n4 + 255) / 256, 256>>>(x, Xhi, Xlo, n4);
    transpose4_split<<<dim3(32, 32, 4), dim3(32, 8)>>>(Wq, Wk, Wv, Wo, Whi, Wlo);

    // 2) Q/K/V projections (3xTF32 tensor cores, 3-stage pipeline)
    const dim3 gg(Dc / BN, Mc / BM);   // (8, 32)
    const size_t DD = (size_t)Dc * Dc;
    gemm_3xtf32<1><<<gg, 256, GEMM_SMEM>>>(Xhi, Xlo, Whi + 0 * DD, Wlo + 0 * DD, bq, Qp, nullptr);
    gemm_3xtf32<2><<<gg, 256, GEMM_SMEM>>>(Xhi, Xlo, Whi + 1 * DD, Wlo + 1 * DD, bk, Khi, Klo);
    gemm_3xtf32<1><<<gg, 256, GEMM_SMEM>>>(Xhi, Xlo, Whi + 2 * DD, Wlo + 2 * DD, bv, Vp, nullptr);

    // 3) prep V (transpose + split) for mma attention
    trans_split_V<<<dim3(Tc / 32, HDc / 32, Bc * Hc), dim3(32, 8)>>>(Vp, Vthi, Vtlo);

    // 4) attention (tensor cores, 3xTF32)
    const dim3 ag(Tc / AQ, Bc * Hc);   // (32, 32)
    attn_mma<<<ag, 128, ATTN_SMEM>>>(Qp, Khi, Klo, Vthi, Vtlo, Ahi, Alo);

    // 5) output projection -> d_out
    gemm_3xtf32<0><<<gg, 256, GEMM_SMEM>>>(Ahi, Alo, Whi + 3 * DD, Wlo + 3 * DD, bo, out, nullptr);
}

// round 8
// speedup vs baseline: 3.2586x; 1.0172x over previous
#include <cuda_runtime.h>
#include <cuda_bf16.h>
#include <math.h>
#include <stdint.h>

// Problem constants
constexpr int Bc  = 2;
constexpr int Tc  = 2048;
constexpr int Dc  = 1024;
constexpr int Hc  = 16;
constexpr int HDc = 64;
constexpr int Mc  = Bc * Tc;      // 4096

// ---------------------------------------------------------------------------
// Scratch (device globals; no allocations allowed)
// ---------------------------------------------------------------------------
__device__ float g_Xhi[Mc * Dc];              // k-permuted
__device__ float g_Xlo[Mc * Dc];
__device__ float g_Q[Bc * Hc * Tc * HDc];     // raw
__device__ float g_V[Bc * Hc * Tc * HDc];     // raw
__device__ float g_Khi[Bc * Hc * Tc * HDc];   // d-permuted
__device__ float g_Klo[Bc * Hc * Tc * HDc];
__device__ float g_Vthi[Bc * Hc * Tc * HDc];  // [bh][d][t], t-permuted
__device__ float g_Vtlo[Bc * Hc * Tc * HDc];
__device__ float g_Ahi[Bc * Tc * Dc];         // D-permuted
__device__ float g_Alo[Bc * Tc * Dc];
__device__ float g_Wthi[4 * Dc * Dc];         // [n][k], k-permuted
__device__ float g_Wtlo[4 * Dc * Dc];

// ---------------------------------------------------------------------------
// Helpers
// ---------------------------------------------------------------------------
__device__ __forceinline__ float tf32r(float x) {
    uint32_t r;
    asm("cvt.rna.tf32.f32 %0, %1;" : "=r"(r) : "f"(x));
    return __uint_as_float(r);
}

// pair-permutation within 8-blocks: j -> 2*(j&3) + (j>>2)
__device__ __forceinline__ int fperm(int j) { return ((j & 3) << 1) | ((j >> 2) & 1); }
__device__ __forceinline__ int permc(int c) { return (c & ~7) | fperm(c & 7); }

__device__ __forceinline__ uint32_t smem_to_u32(const void* p) {
    uint32_t a;
    asm("{ .reg .u64 t; cvta.to.shared.u64 t, %1; cvt.u32.u64 %0, t; }" : "=r"(a) : "l"(p));
    return a;
}

__device__ __forceinline__ void cp_async16(uint32_t saddr, const void* gaddr) {
    asm volatile("cp.async.cg.shared.global [%0], [%1], 16;" :: "r"(saddr), "l"(gaddr));
}
__device__ __forceinline__ void cp_commit() {
    asm volatile("cp.async.commit_group;" ::: "memory");
}
template <int N>
__device__ __forceinline__ void cp_wait() {
    asm volatile("cp.async.wait_group %0;" :: "n"(N) : "memory");
}

// tf32 m16n8k8 mma.sync
__device__ __forceinline__ void mma_tf32(float* d, const uint32_t* a, const uint32_t* b) {
    asm volatile(
        "mma.sync.aligned.m16n8k8.row.col.f32.tf32.tf32.f32 "
        "{%0,%1,%2,%3}, {%4,%5,%6,%7}, {%8,%9}, {%0,%1,%2,%3};"
        : "+f"(d[0]), "+f"(d[1]), "+f"(d[2]), "+f"(d[3])
        : "r"(a[0]), "r"(a[1]), "r"(a[2]), "r"(a[3]), "r"(b[0]), "r"(b[1]));
}

// ---------------------------------------------------------------------------
// Prep: split X into tf32 hi/lo with k-pair permutation of the last dim
// ---------------------------------------------------------------------------
__global__ __launch_bounds__(256)
void split_permK_kernel(const float* __restrict__ in, float* __restrict__ hi,
                        float* __restrict__ lo, int n4)
{
    int i = blockIdx.x * 256 + threadIdx.x;
    if (i < n4) {
        const int flat = i * 4;
        float4 v = ((const float4*)in)[i];
        const int o = (flat & ~7) + ((flat & 4) ? 1 : 0);   // fperm(4s+e) = 2e+s
        float h, l;
        h = tf32r(v.x); l = tf32r(v.x - h); hi[o + 0] = h; lo[o + 0] = l;
        h = tf32r(v.y); l = tf32r(v.y - h); hi[o + 2] = h; lo[o + 2] = l;
        h = tf32r(v.z); l = tf32r(v.z - h); hi[o + 4] = h; lo[o + 4] = l;
        h = tf32r(v.w); l = tf32r(v.w - h); hi[o + 6] = h; lo[o + 6] = l;
    }
}

// ---------------------------------------------------------------------------
// Prep: per-head transpose+split of V, with t-pair permutation:
//   Vt[bh][d][perm(t)] = split(V[bh][t][d])
// ---------------------------------------------------------------------------
__global__ __launch_bounds__(256)
void trans_split_V(const float* __restrict__ V, float* __restrict__ Thi,
                   float* __restrict__ Tlo)
{
    __shared__ float tile[32][33];
    const int bh = blockIdx.z;
    const int t0 = blockIdx.x * 32, d0 = blockIdx.y * 32;
    const int tx = threadIdx.x, ty = threadIdx.y;
    const float* src = V + (size_t)bh * Tc * HDc;
    #pragma unroll
    for (int j = 0; j < 32; j += 8)
        tile[ty + j][tx] = src[(size_t)(t0 + ty + j) * HDc + d0 + tx];
    __syncthreads();
    float* dh = Thi + (size_t)bh * HDc * Tc;
    float* dl = Tlo + (size_t)bh * HDc * Tc;
    const int txp = permc(tx);
    #pragma unroll
    for (int j = 0; j < 32; j += 8) {
        const float v = tile[tx][ty + j];
        const float h = tf32r(v);
        dh[(size_t)(d0 + ty + j) * Tc + t0 + txp] = h;
        dl[(size_t)(d0 + ty + j) * Tc + t0 + txp] = tf32r(v - h);
    }
}

// ---------------------------------------------------------------------------
// Weight transpose + split + k-pair permutation: Wt[n][perm(k)] = split(W[k][n])
// ---------------------------------------------------------------------------
__global__ __launch_bounds__(256)
void transpose4_split(const float* __restrict__ W0, const float* __restrict__ W1,
                      const float* __restrict__ W2, const float* __restrict__ W3,
                      float* __restrict__ Thi, float* __restrict__ Tlo)
{
    __shared__ float tile[32][33];
    const int z = blockIdx.z;
    const float* W = (z == 0) ? W0 : (z == 1) ? W1 : (z == 2) ? W2 : W3;
    const size_t zoff = (size_t)z * Dc * Dc;

    const int tx = threadIdx.x, ty = threadIdx.y;
    int x = blockIdx.x * 32 + tx;
    int y = blockIdx.y * 32 + ty;
    #pragma unroll
    for (int j = 0; j < 32; j += 8)
        tile[ty + j][tx] = W[(size_t)(y + j) * Dc + x];
    __syncthreads();
    const int xp = blockIdx.y * 32 + permc(tx);   // permuted k column
    y = blockIdx.x * 32 + ty;
    #pragma unroll
    for (int j = 0; j < 32; j += 8) {
        const float v = tile[tx][ty + j];
        const float h = tf32r(v);
        Thi[zoff + (size_t)(y + j) * Dc + xp] = h;
        Tlo[zoff + (size_t)(y + j) * Dc + xp] = tf32r(v - h);
    }
}

// ---------------------------------------------------------------------------
// 3xTF32 mma.sync GEMM:  Y = X @ Wt^T + bias   (all operands k-pair-permuted)
// CTA 128x128, BK=32, 2-stage cp.async, 8 warps, warp 64x32, LDS.64 fragments.
// MODE: 0 = flat raw; 1 = head-split raw; 2 = head-split + hi/lo + d-permuted
// ---------------------------------------------------------------------------
constexpr int BM = 128, BN = 128, BKC = 32;
constexpr int NCH = Dc / BKC;            // 32
constexpr int SST = 40;                  // row stride (floats): (4g+tg) 8B-banks
constexpr int TILE_F = BM * SST;         // 5120
constexpr int STAGE_F = 4 * TILE_F;      // Ahi, Alo, Bhi, Blo
constexpr int GEMM_SMEM = 2 * STAGE_F * 4;   // 163840 B

template <int MODE>
__global__ __launch_bounds__(256, 1)
void gemm_3xtf32(const float* __restrict__ Xhi, const float* __restrict__ Xlo,
                 const float* __restrict__ Whi, const float* __restrict__ Wlo,
                 const float* __restrict__ bias,
                 float* __restrict__ Y, float* __restrict__ Y2)
{
    extern __shared__ __align__(16) float smem[];
    const uint32_t sb = smem_to_u32(smem);
    const int tid = threadIdx.x;
    const int wid = tid >> 5, lane = tid & 31;
    const int g = lane >> 2, tg = lane & 3;
    const int wm = wid & 1;
    const int wn = wid >> 1;
    const int m0 = blockIdx.y * BM;
    const int n0 = blockIdx.x * BN;

    auto load_chunk = [&](int k, int s) {
        const uint32_t sbase = sb + (uint32_t)s * STAGE_F * 4;
        const size_t aoff = (size_t)m0 * Dc + k * BKC;
        const size_t boff = (size_t)n0 * Dc + k * BKC;
        const float* srcs[4] = {Xhi + aoff, Xlo + aoff, Whi + boff, Wlo + boff};
        #pragma unroll
        for (int t = 0; t < 4; t++) {
            const float* gsrc = srcs[t];
            const uint32_t tbase = sbase + (uint32_t)t * TILE_F * 4;
            #pragma unroll
            for (int i = 0; i < 4; i++) {
                const int u = i * 256 + tid;
                const int row = u >> 3, kc = (u & 7) << 2;
                cp_async16(tbase + (uint32_t)(row * SST + kc) * 4,
                           gsrc + (size_t)row * Dc + kc);
            }
        }
        cp_commit();
    };

    float acc[4][4][4] = {};

    load_chunk(0, 0);
    load_chunk(1, 1);

    for (int k = 0; k < NCH; k++) {
        const int s = k & 1;
        cp_wait<1>();
        __syncthreads();

        const float* Ahi = smem + s * STAGE_F;
        const float* Alo = Ahi + TILE_F;
        const float* Bhi = Alo + TILE_F;
        const float* Blo = Bhi + TILE_F;

        #pragma unroll
        for (int kk = 0; kk < 4; kk++) {
            const int kb = kk * 8;
            uint32_t ah[4][4], al[4][4], bh[4][2], bl[4][2];
            #pragma unroll
            for (int mi = 0; mi < 4; mi++) {
                const int r0 = (wm * 64 + mi * 16 + g) * SST + kb + 2 * tg;
                const int r1 = r0 + 8 * SST;
                const float2 h0 = *(const float2*)&Ahi[r0];   // (k=tg, k=tg+4)
                const float2 h1 = *(const float2*)&Ahi[r1];
                const float2 l0 = *(const float2*)&Alo[r0];
                const float2 l1 = *(const float2*)&Alo[r1];
                ah[mi][0] = __float_as_uint(h0.x); ah[mi][1] = __float_as_uint(h1.x);
                ah[mi][2] = __float_as_uint(h0.y); ah[mi][3] = __float_as_uint(h1.y);
                al[mi][0] = __float_as_uint(l0.x); al[mi][1] = __float_as_uint(l1.x);
                al[mi][2] = __float_as_uint(l0.y); al[mi][3] = __float_as_uint(l1.y);
            }
            #pragma unroll
            for (int ni = 0; ni < 4; ni++) {
                const int rb = (wn * 32 + ni * 8 + g) * SST + kb + 2 * tg;
                const float2 hb = *(const float2*)&Bhi[rb];
                const float2 lb = *(const float2*)&Blo[rb];
                bh[ni][0] = __float_as_uint(hb.x); bh[ni][1] = __float_as_uint(hb.y);
                bl[ni][0] = __float_as_uint(lb.x); bl[ni][1] = __float_as_uint(lb.y);
            }
            #pragma unroll
            for (int mi = 0; mi < 4; mi++)
                #pragma unroll
                for (int ni = 0; ni < 4; ni++) {
                    mma_tf32(acc[mi][ni], al[mi], bh[ni]);
                    mma_tf32(acc[mi][ni], ah[mi], bl[ni]);
                    mma_tf32(acc[mi][ni], ah[mi], bh[ni]);
                }
        }

        __syncthreads();
        if (k + 2 < NCH) load_chunk(k + 2, s); else cp_commit();
    }

    #pragma unroll
    for (int mi = 0; mi < 4; mi++) {
        const int row0 = m0 + wm * 64 + mi * 16 + g;
        #pragma unroll
        for (int ni = 0; ni < 4; ni++) {
            const int col = n0 + wn * 32 + ni * 8 + 2 * tg;
            const float2 bv = *(const float2*)&bias[col];
            float2 v0, v1;
            v0.x = acc[mi][ni][0] + bv.x;  v0.y = acc[mi][ni][1] + bv.y;
            v1.x = acc[mi][ni][2] + bv.x;  v1.y = acc[mi][ni][3] + bv.y;
            if (MODE == 0) {
                *(float2*)(Y + (size_t)row0 * Dc + col) = v0;
                *(float2*)(Y + (size_t)(row0 + 8) * Dc + col) = v1;
            } else {
                const int h = col >> 6, d0 = col & 63;
                const int b0i = row0 >> 11, t0 = row0 & 2047;
                const size_t q0 = (((size_t)b0i * Hc + h) * Tc + t0) << 6;
                const int row1 = row0 + 8;
                const int b1i = row1 >> 11, t1 = row1 & 2047;
                const size_t q1 = (((size_t)b1i * Hc + h) * Tc + t1) << 6;
                if (MODE == 1) {
                    *(float2*)(Y + q0 + d0) = v0;
                    *(float2*)(Y + q1 + d0) = v1;
                } else {
                    const int dp0 = permc(d0);
                    const int dp1 = permc(d0 + 1);
                    float h_, l_;
                    h_ = tf32r(v0.x); l_ = tf32r(v0.x - h_); Y[q0 + dp0] = h_; Y2[q0 + dp0] = l_;
                    h_ = tf32r(v0.y); l_ = tf32r(v0.y - h_); Y[q0 + dp1] = h_; Y2[q0 + dp1] = l_;
                    h_ = tf32r(v1.x); l_ = tf32r(v1.x - h_); Y[q1 + dp0] = h_; Y2[q1 + dp0] = l_;
                    h_ = tf32r(v1.y); l_ = tf32r(v1.y - h_); Y[q1 + dp1] = h_; Y2[q1 + dp1] = l_;
                }
            }
        }
    }
}

// ---------------------------------------------------------------------------
// mma.sync flash attention (3xTF32), causal, paired LDS.64 fragment loads.
// ---------------------------------------------------------------------------
constexpr int AQ  = 64;
constexpr int AKT = 32;
constexpr int KSTr = 72;                 // K tile stride: 36 8B-units, 36%16=4
constexpr int VSTr = 40;                 // Vt tile stride: 20 8B-units
constexpr int KTILE_F = AKT * KSTr;      // 2304
constexpr int VTILE_F = HDc * VSTr;      // 2560
constexpr int ASTAGE_F = 2 * KTILE_F + 2 * VTILE_F;  // 9728
constexpr int P_OFF = 2 * ASTAGE_F;      // 19456
constexpr int ATTN_SMEM = (P_OFF + 4 * 16 * 36) * 4; // 87040 B

__global__ __launch_bounds__(128)
void attn_mma(const float* __restrict__ Q,
              const float* __restrict__ Khi, const float* __restrict__ Klo,
              const float* __restrict__ Vthi, const float* __restrict__ Vtlo,
              float* __restrict__ Ohi, float* __restrict__ Olo)
{
    extern __shared__ __align__(16) float as_[];
    const uint32_t sb = smem_to_u32(as_);
    const int tid = threadIdx.x, wid = tid >> 5, lane = tid & 31;
    const int g = lane >> 2, tg = lane & 3;
    const int bh = blockIdx.y;
    const int q0 = (int)(gridDim.x - 1 - blockIdx.x) * AQ;   // longest tiles first
    const int b = bh >> 4, h = bh & 15;
    const int nt = q0 / AKT + 2;

    // Q fragments (raw gmem), scaled, split hi/lo, resident
    uint32_t qhi[8][4], qlo[8][4];
    {
        const float* qb = Q + ((size_t)bh * Tc + q0 + wid * 16) * HDc;
        #pragma unroll
        for (int kc = 0; kc < 8; kc++) {
            const int c0 = kc * 8 + tg;
            float v[4];
            v[0] = qb[(size_t)g * HDc + c0] * 0.125f;
            v[1] = qb[(size_t)(g + 8) * HDc + c0] * 0.125f;
            v[2] = qb[(size_t)g * HDc + c0 + 4] * 0.125f;
            v[3] = qb[(size_t)(g + 8) * HDc + c0 + 4] * 0.125f;
            #pragma unroll
            for (int r = 0; r < 4; r++) {
                const float hv = tf32r(v[r]);
                qhi[kc][r] = __float_as_uint(hv);
                qlo[kc][r] = __float_as_uint(tf32r(v[r] - hv));
            }
        }
    }

    auto load_stage = [&](int t_, int s_) {
        const uint32_t base = sb + (uint32_t)(s_ * ASTAGE_F) * 4;
        const int k0_ = t_ * AKT;
        const size_t kg = ((size_t)bh * Tc + k0_) * HDc;
        const size_t vg = (size_t)bh * HDc * Tc + k0_;
        #pragma unroll
        for (int i = 0; i < 4; i++) {
            const int u = i * 128 + tid;
            const int r = u >> 4, c = (u & 15) * 4;
            cp_async16(base + (uint32_t)(r * KSTr + c) * 4, Khi + kg + (size_t)r * HDc + c);
        }
        #pragma unroll
        for (int i = 0; i < 4; i++) {
            const int u = i * 128 + tid;
            const int r = u >> 4, c = (u & 15) * 4;
            cp_async16(base + (uint32_t)(KTILE_F + r * KSTr + c) * 4, Klo + kg + (size_t)r * HDc + c);
        }
        #pragma unroll
        for (int i = 0; i < 4; i++) {
            const int u = i * 128 + tid;
            const int r = u >> 3, c = (u & 7) * 4;
            cp_async16(base + (uint32_t)(2 * KTILE_F + r * VSTr + c) * 4,
                       Vthi + vg + (size_t)r * Tc + c);
        }
        #pragma unroll
        for (int i = 0; i < 4; i++) {
            const int u = i * 128 + tid;
            const int r = u >> 3, c = (u & 7) * 4;
            cp_async16(base + (uint32_t)(2 * KTILE_F + VTILE_F + r * VSTr + c) * 4,
                       Vtlo + vg + (size_t)r * Tc + c);
        }
        cp_commit();
    };

    float acc_o[8][4] = {};
    float m0 = -INFINITY, m1 = -INFINITY, l0 = 0.f, l1 = 0.f;
    const int row0 = q0 + wid * 16 + g;

    load_stage(0, 0);
    if (nt > 1) load_stage(1, 1); else cp_commit();

    for (int t = 0; t < nt; t++) {
        const int s = t & 1;
        const int k0 = t * AKT;
        cp_wait<1>();
        __syncthreads();

        const float* Ks_hi = as_ + s * ASTAGE_F;
        const float* Ks_lo = Ks_hi + KTILE_F;
        const float* Vs_hi = Ks_hi + 2 * KTILE_F;
        const float* Vs_lo = Vs_hi + VTILE_F;
        float* Pw = as_ + P_OFF + wid * (16 * 36);

        // ---- S = Q @ K^T (3xTF32, paired K loads) ----
        float sacc[4][4] = {};
        #pragma unroll
        for (int kc = 0; kc < 8; kc++) {
            #pragma unroll
            for (int n_ = 0; n_ < 4; n_++) {
                const int bi = (n_ * 8 + g) * KSTr + kc * 8 + 2 * tg;
                const float2 kh2 = *(const float2*)&Ks_hi[bi];
                const float2 kl2 = *(const float2*)&Ks_lo[bi];
                uint32_t kh[2], kl[2];
                kh[0] = __float_as_uint(kh2.x); kh[1] = __float_as_uint(kh2.y);
                kl[0] = __float_as_uint(kl2.x); kl[1] = __float_as_uint(kl2.y);
                mma_tf32(sacc[n_], qlo[kc], kh);
                mma_tf32(sacc[n_], qhi[kc], kl);
                mma_tf32(sacc[n_], qhi[kc], kh);
            }
        }

        // ---- causal mask ----
        if (k0 + AKT - 1 > q0 + wid * 16) {
            #pragma unroll
            for (int n_ = 0; n_ < 4; n_++) {
                const int c0 = k0 + n_ * 8 + 2 * tg;
                if (c0 > row0)     sacc[n_][0] = -1e30f;
                if (c0 + 1 > row0) sacc[n_][1] = -1e30f;
                if (c0 > row0 + 8)     sacc[n_][2] = -1e30f;
                if (c0 + 1 > row0 + 8) sacc[n_][3] = -1e30f;
            }
        }

        // ---- online softmax ----
        float tx0 = sacc[0][0], tx1 = sacc[0][2];
        #pragma unroll
        for (int n_ = 0; n_ < 4; n_++) {
            tx0 = fmaxf(tx0, fmaxf(sacc[n_][0], sacc[n_][1]));
            tx1 = fmaxf(tx1, fmaxf(sacc[n_][2], sacc[n_][3]));
        }
        tx0 = fmaxf(tx0, __shfl_xor_sync(0xffffffffu, tx0, 1));
        tx0 = fmaxf(tx0, __shfl_xor_sync(0xffffffffu, tx0, 2));
        tx1 = fmaxf(tx1, __shfl_xor_sync(0xffffffffu, tx1, 1));
        tx1 = fmaxf(tx1, __shfl_xor_sync(0xffffffffu, tx1, 2));
        const float mn0 = fmaxf(m0, tx0), mn1 = fmaxf(m1, tx1);
        const float c0f = __expf(m0 - mn0), c1f = __expf(m1 - mn1);
        m0 = mn0; m1 = mn1;

        float rs0 = 0.f, rs1 = 0.f;
        #pragma unroll
        for (int n_ = 0; n_ < 4; n_++) {
            const float p0 = __expf(sacc[n_][0] - mn0);
            const float p1 = __expf(sacc[n_][1] - mn0);
            const float p2 = __expf(sacc[n_][2] - mn1);
            const float p3 = __expf(sacc[n_][3] - mn1);
            rs0 += p0 + p1; rs1 += p2 + p3;
            float2 w0; w0.x = p0; w0.y = p1;
            float2 w1; w1.x = p2; w1.y = p3;
            *(float2*)&Pw[g * 36 + n_ * 8 + 2 * tg] = w0;
            *(float2*)&Pw[(g + 8) * 36 + n_ * 8 + 2 * tg] = w1;
        }
        rs0 += __shfl_xor_sync(0xffffffffu, rs0, 1);
        rs0 += __shfl_xor_sync(0xffffffffu, rs0, 2);
        rs1 += __shfl_xor_sync(0xffffffffu, rs1, 1);
        rs1 += __shfl_xor_sync(0xffffffffu, rs1, 2);
        l0 = l0 * c0f + rs0;
        l1 = l1 * c1f + rs1;

        #pragma unroll
        for (int d8 = 0; d8 < 8; d8++) {
            acc_o[d8][0] *= c0f; acc_o[d8][1] *= c0f;
            acc_o[d8][2] *= c1f; acc_o[d8][3] *= c1f;
        }
        __syncwarp();

        // ---- O += P @ V (3xTF32, paired V loads) ----
        #pragma unroll
        for (int kc = 0; kc < 4; kc++) {
            float pv[4];
            pv[0] = Pw[g * 36 + kc * 8 + tg];
            pv[1] = Pw[(g + 8) * 36 + kc * 8 + tg];
            pv[2] = Pw[g * 36 + kc * 8 + tg + 4];
            pv[3] = Pw[(g + 8) * 36 + kc * 8 + tg + 4];
            uint32_t ah[4], al[4];
            #pragma unroll
            for (int r = 0; r < 4; r++) {
                const float hv = tf32r(pv[r]);
                ah[r] = __float_as_uint(hv);
                al[r] = __float_as_uint(tf32r(pv[r] - hv));
            }
            #pragma unroll
            for (int d8 = 0; d8 < 8; d8++) {
                const int bi = (d8 * 8 + g) * VSTr + kc * 8 + 2 * tg;
                const float2 vh2 = *(const float2*)&Vs_hi[bi];
                const float2 vl2 = *(const float2*)&Vs_lo[bi];
                uint32_t vh[2], vl[2];
                vh[0] = __float_as_uint(vh2.x); vh[1] = __float_as_uint(vh2.y);
                vl[0] = __float_as_uint(vl2.x); vl[1] = __float_as_uint(vl2.y);
                mma_tf32(acc_o[d8], al, vh);
                mma_tf32(acc_o[d8], ah, vl);
                mma_tf32(acc_o[d8], ah, vh);
            }
        }
        __syncwarp();

        __syncthreads();
        if (t + 2 < nt) load_stage(t + 2, s); else cp_commit();
    }

    // ---- epilogue: O/l, split hi/lo, merge heads, D-pair-permute cols ----
    const float il0 = 1.f / l0, il1 = 1.f / l1;
    const size_t ob0 = ((size_t)b * Tc + row0) * Dc + (size_t)h * HDc;
    const size_t ob1 = ob0 + (size_t)8 * Dc;
    #pragma unroll
    for (int d8 = 0; d8 < 8; d8++) {
        const int c = d8 * 8 + 2 * tg;
        const int cp0 = permc(c), cp1 = permc(c + 1);
        float v0 = acc_o[d8][0] * il0, v1 = acc_o[d8][1] * il0;
        float v2 = acc_o[d8][2] * il1, v3 = acc_o[d8][3] * il1;
        float h_, l_;
        h_ = tf32r(v0); l_ = tf32r(v0 - h_); Ohi[ob0 + cp0] = h_; Olo[ob0 + cp0] = l_;
        h_ = tf32r(v1); l_ = tf32r(v1 - h_); Ohi[ob0 + cp1] = h_; Olo[ob0 + cp1] = l_;
        h_ = tf32r(v2); l_ = tf32r(v2 - h_); Ohi[ob1 + cp0] = h_; Olo[ob1 + cp0] = l_;
        h_ = tf32r(v3); l_ = tf32r(v3 - h_); Ohi[ob1 + cp1] = h_; Olo[ob1 + cp1] = l_;
    }
}

// ---------------------------------------------------------------------------
// Launch
// ---------------------------------------------------------------------------
extern "C" void kernel_launch(void* const* d_in, const int* in_sizes, int n_in,
                              void* d_out, int out_size)
{
    const float* x  = (const float*)d_in[0];
    const float* Wq = (const float*)d_in[1];
    const float* bq = (const float*)d_in[2];
    const float* Wk = (const float*)d_in[3];
    const float* bk = (const float*)d_in[4];
    const float* Wv = (const float*)d_in[5];
    const float* bv = (const float*)d_in[6];
    const float* Wo = (const float*)d_in[7];
    const float* bo = (const float*)d_in[8];
    float* out = (float*)d_out;

    float *Xhi, *Xlo, *Qp, *Vp, *Khi, *Klo, *Vthi, *Vtlo, *Ahi, *Alo, *Whi, *Wlo;
    cudaGetSymbolAddress((void**)&Xhi, g_Xhi);
    cudaGetSymbolAddress((void**)&Xlo, g_Xlo);
    cudaGetSymbolAddress((void**)&Qp, g_Q);
    cudaGetSymbolAddress((void**)&Vp, g_V);
    cudaGetSymbolAddress((void**)&Khi, g_Khi);
    cudaGetSymbolAddress((void**)&Klo, g_Klo);
    cudaGetSymbolAddress((void**)&Vthi, g_Vthi);
    cudaGetSymbolAddress((void**)&Vtlo, g_Vtlo);
    cudaGetSymbolAddress((void**)&Ahi, g_Ahi);
    cudaGetSymbolAddress((void**)&Alo, g_Alo);
    cudaGetSymbolAddress((void**)&Whi, g_Wthi);
    cudaGetSymbolAddress((void**)&Wlo, g_Wtlo);

    cudaFuncSetAttribute(gemm_3xtf32<0>, cudaFuncAttributeMaxDynamicSharedMemorySize, GEMM_SMEM);
    cudaFuncSetAttribute(gemm_3xtf32<1>, cudaFuncAttributeMaxDynamicSharedMemorySize, GEMM_SMEM);
    cudaFuncSetAttribute(gemm_3xtf32<2>, cudaFuncAttributeMaxDynamicSharedMemorySize, GEMM_SMEM);
    cudaFuncSetAttribute(attn_mma, cudaFuncAttributeMaxDynamicSharedMemorySize, ATTN_SMEM);

    // 1) prep: split+permute X; transpose+split+permute weights
    const int n4 = Mc * Dc / 4;
    split_permK_kernel<<<(n4 + 255) / 256, 256>>>(x, Xhi, Xlo, n4);
    transpose4_split<<<dim3(32, 32, 4), dim3(32, 8)>>>(Wq, Wk, Wv, Wo, Whi, Wlo);

    // 2) Q/K/V projections
    const dim3 gg(Dc / BN, Mc / BM);   // (8, 32)
    const size_t DD = (size_t)Dc * Dc;
    gemm_3xtf32<1><<<gg, 256, GEMM_SMEM>>>(Xhi, Xlo, Whi + 0 * DD, Wlo + 0 * DD, bq, Qp, nullptr);
    gemm_3xtf32<2><<<gg, 256, GEMM_SMEM>>>(Xhi, Xlo, Whi + 1 * DD, Wlo + 1 * DD, bk, Khi, Klo);
    gemm_3xtf32<1><<<gg, 256, GEMM_SMEM>>>(Xhi, Xlo, Whi + 2 * DD, Wlo + 2 * DD, bv, Vp, nullptr);

    // 3) prep V (transpose + split + t-permute)
    trans_split_V<<<dim3(Tc / 32, HDc / 32, Bc * Hc), dim3(32, 8)>>>(Vp, Vthi, Vtlo);

    // 4) attention
    const dim3 ag(Tc / AQ, Bc * Hc);   // (32, 32)
    attn_mma<<<ag, 128, ATTN_SMEM>>>(Qp, Khi, Klo, Vthi, Vtlo, Ahi, Alo);

    // 5) output projection -> d_out
    gemm_3xtf32<0><<<gg, 256, GEMM_SMEM>>>(Ahi, Alo, Whi + 3 * DD, Wlo + 3 * DD, bo, out, nullptr);
}

// round 9
// speedup vs baseline: 6.0550x; 1.8581x over previous
#include <cuda_runtime.h>
#include <cuda_bf16.h>
#include <math.h>
#include <stdint.h>

// Problem constants
constexpr int Bc  = 2;
constexpr int Tc  = 2048;
constexpr int Dc  = 1024;
constexpr int Hc  = 16;
constexpr int HDc = 64;
constexpr int Mc  = Bc * Tc;      // 4096

// ---------------------------------------------------------------------------
// Scratch (device globals; no allocations allowed)
// ---------------------------------------------------------------------------
__device__ __nv_bfloat16 g_Xhi[Mc * Dc];             // k-pair-permuted
__device__ __nv_bfloat16 g_Xlo[Mc * Dc];
__device__ float         g_Q[Bc * Hc * Tc * HDc];    // raw f32
__device__ float         g_V[Bc * Hc * Tc * HDc];    // raw f32
__device__ __nv_bfloat16 g_Khi[Bc * Hc * Tc * HDc];  // d-pair-permuted
__device__ __nv_bfloat16 g_Klo[Bc * Hc * Tc * HDc];
__device__ __nv_bfloat16 g_Vthi[Bc * Hc * Tc * HDc]; // [bh][d][t], t-permuted
__device__ __nv_bfloat16 g_Vtlo[Bc * Hc * Tc * HDc];
__device__ __nv_bfloat16 g_Ahi[Mc * Dc];             // D-pair-permuted
__device__ __nv_bfloat16 g_Alo[Mc * Dc];
__device__ __nv_bfloat16 g_Wthi[4 * Dc * Dc];        // [n][k], k-permuted
__device__ __nv_bfloat16 g_Wtlo[4 * Dc * Dc];

// ---------------------------------------------------------------------------
// Helpers
// ---------------------------------------------------------------------------
// pair permutation within 16-blocks: element c -> pair p=(c>>1)&7 goes to
// position fp(p)=2*(p&3)+(p>>2); thread tg then reads pairs (tg, tg+4) as
// 4 contiguous elements at offset 4*tg.
__device__ __host__ __forceinline__ int perm16(int c) {
    const int p = (c >> 1) & 7, e = c & 1;
    const int fp = ((p & 3) << 1) | (p >> 2);
    return (c & ~15) | (fp << 1) | e;
}

__device__ __forceinline__ uint32_t smem_to_u32(const void* p) {
    uint32_t a;
    asm("{ .reg .u64 t; cvta.to.shared.u64 t, %1; cvt.u32.u64 %0, t; }" : "=r"(a) : "l"(p));
    return a;
}

__device__ __forceinline__ void cp_async16(uint32_t saddr, const void* gaddr) {
    asm volatile("cp.async.cg.shared.global [%0], [%1], 16;" :: "r"(saddr), "l"(gaddr));
}
__device__ __forceinline__ void cp_commit() {
    asm volatile("cp.async.commit_group;" ::: "memory");
}
template <int N>
__device__ __forceinline__ void cp_wait() {
    asm volatile("cp.async.wait_group %0;" :: "n"(N) : "memory");
}

// bf16 m16n8k16 mma.sync (sm_80+)
__device__ __forceinline__ void mma_bf16(float* d, const uint32_t* a, const uint32_t* b) {
    asm volatile(
        "mma.sync.aligned.m16n8k16.row.col.f32.bf16.bf16.f32 "
        "{%0,%1,%2,%3}, {%4,%5,%6,%7}, {%8,%9}, {%0,%1,%2,%3};"
        : "+f"(d[0]), "+f"(d[1]), "+f"(d[2]), "+f"(d[3])
        : "r"(a[0]), "r"(a[1]), "r"(a[2]), "r"(a[3]), "r"(b[0]), "r"(b[1]));
}

__device__ __forceinline__ void split_bf16(float v, __nv_bfloat16& h, __nv_bfloat16& l) {
    h = __float2bfloat16_rn(v);
    l = __float2bfloat16_rn(v - __bfloat162float(h));
}
__device__ __forceinline__ uint32_t pack2(__nv_bfloat16 a, __nv_bfloat16 b) {
    __nv_bfloat162 t; t.x = a; t.y = b;
    return *(uint32_t*)&t;
}

// ---------------------------------------------------------------------------
// Prep: split X (f32 [M,1024]) into bf16 hi/lo, k-pair-permuted. 1 pair/thread.
// ---------------------------------------------------------------------------
__global__ __launch_bounds__(256)
void split_permK_bf16(const float* __restrict__ in, __nv_bfloat16* __restrict__ hi,
                      __nv_bfloat16* __restrict__ lo, int n2)
{
    int i = blockIdx.x * 256 + threadIdx.x;
    if (i < n2) {
        const int j = 2 * i;
        const float2 v = *(const float2*)(in + j);
        const int p = (j >> 1) & 7;
        const int newj = (j & ~15) | ((((p & 3) << 1) | (p >> 2)) << 1);
        __nv_bfloat162 h, l;
        split_bf16(v.x, h.x, l.x);
        split_bf16(v.y, h.y, l.y);
        *(__nv_bfloat162*)(hi + newj) = h;
        *(__nv_bfloat162*)(lo + newj) = l;
    }
}

// ---------------------------------------------------------------------------
// Prep: per-head transpose+split of V: Vt[bh][d][perm16(t)] = split(V[bh][t][d])
// ---------------------------------------------------------------------------
__global__ __launch_bounds__(256)
void trans_split_V(const float* __restrict__ V, __nv_bfloat16* __restrict__ Thi,
                   __nv_bfloat16* __restrict__ Tlo)
{
    __shared__ float tile[32][33];
    const int bh = blockIdx.z;
    const int t0 = blockIdx.x * 32, d0 = blockIdx.y * 32;
    const int tx = threadIdx.x, ty = threadIdx.y;
    const float* src = V + (size_t)bh * Tc * HDc;
    #pragma unroll
    for (int j = 0; j < 32; j += 8)
        tile[ty + j][tx] = src[(size_t)(t0 + ty + j) * HDc + d0 + tx];
    __syncthreads();
    __nv_bfloat16* dh = Thi + (size_t)bh * HDc * Tc;
    __nv_bfloat16* dl = Tlo + (size_t)bh * HDc * Tc;
    const int txp = t0 + perm16(tx);
    #pragma unroll
    for (int j = 0; j < 32; j += 8) {
        __nv_bfloat16 h, l;
        split_bf16(tile[tx][ty + j], h, l);
        dh[(size_t)(d0 + ty + j) * Tc + txp] = h;
        dl[(size_t)(d0 + ty + j) * Tc + txp] = l;
    }
}

// ---------------------------------------------------------------------------
// Weight transpose + split + k-pair perm: Wt[n][perm16(k)] = split(W[k][n])
// ---------------------------------------------------------------------------
__global__ __launch_bounds__(256)
void transpose4_split(const float* __restrict__ W0, const float* __restrict__ W1,
                      const float* __restrict__ W2, const float* __restrict__ W3,
                      __nv_bfloat16* __restrict__ Thi, __nv_bfloat16* __restrict__ Tlo)
{
    __shared__ float tile[32][33];
    const int z = blockIdx.z;
    const float* W = (z == 0) ? W0 : (z == 1) ? W1 : (z == 2) ? W2 : W3;
    const size_t zoff = (size_t)z * Dc * Dc;

    const int tx = threadIdx.x, ty = threadIdx.y;
    int x = blockIdx.x * 32 + tx;
    int y = blockIdx.y * 32 + ty;
    #pragma unroll
    for (int j = 0; j < 32; j += 8)
        tile[ty + j][tx] = W[(size_t)(y + j) * Dc + x];
    __syncthreads();
    const int xp = blockIdx.y * 32 + perm16(tx);   // permuted k column
    y = blockIdx.x * 32 + ty;
    #pragma unroll
    for (int j = 0; j < 32; j += 8) {
        __nv_bfloat16 h, l;
        split_bf16(tile[tx][ty + j], h, l);
        Thi[zoff + (size_t)(y + j) * Dc + xp] = h;
        Tlo[zoff + (size_t)(y + j) * Dc + xp] = l;
    }
}

// ---------------------------------------------------------------------------
// split-bf16 (3-term) GEMM:  Y = X @ Wt^T + bias
// CTA 128x128, BK=64, 2-stage cp.async, 8 warps (2m x 4n), m16n8k16 MMAs.
// MODE: 0 = flat f32; 1 = head-split f32; 2 = head-split bf16 hi/lo d-permuted
// ---------------------------------------------------------------------------
constexpr int BM = 128, BN = 128, BKC2 = 64;
constexpr int NCH2 = Dc / BKC2;          // 16
constexpr int RSG = 80;                  // bf16 elements per smem row (160B)
constexpr int TILE_E = BM * RSG;         // 10240 elements
constexpr int STAGE_E = 4 * TILE_E;      // Ahi, Alo, Bhi, Blo
constexpr int GEMM_SMEM = 2 * STAGE_E * 2;   // 163840 B

template <int MODE>
__global__ __launch_bounds__(256, 1)
void gemm_bf16x3(const __nv_bfloat16* __restrict__ Xhi, const __nv_bfloat16* __restrict__ Xlo,
                 const __nv_bfloat16* __restrict__ Whi, const __nv_bfloat16* __restrict__ Wlo,
                 const float* __restrict__ bias,
                 float* __restrict__ Y, float* __restrict__ Y2)
{
    extern __shared__ __align__(16) char smem_raw[];
    __nv_bfloat16* smem_bf = (__nv_bfloat16*)smem_raw;
    const uint32_t sb = smem_to_u32(smem_raw);
    const int tid = threadIdx.x;
    const int wid = tid >> 5, lane = tid & 31;
    const int g = lane >> 2, tg = lane & 3;
    const int wm = wid & 1;
    const int wn = wid >> 1;
    const int m0 = blockIdx.y * BM;
    const int n0 = blockIdx.x * BN;

    auto load_chunk = [&](int k, int s) {
        const uint32_t sbase = sb + (uint32_t)s * STAGE_E * 2;
        const size_t aoff = (size_t)m0 * Dc + k * BKC2;
        const size_t boff = (size_t)n0 * Dc + k * BKC2;
        const __nv_bfloat16* srcs[4] = {Xhi + aoff, Xlo + aoff, Whi + boff, Wlo + boff};
        #pragma unroll
        for (int t = 0; t < 4; t++) {
            const __nv_bfloat16* gsrc = srcs[t];
            const uint32_t tbase = sbase + (uint32_t)t * TILE_E * 2;
            #pragma unroll
            for (int i = 0; i < 4; i++) {
                const int u = i * 256 + tid;              // 0..1023
                const int row = u >> 3, c = u & 7;
                cp_async16(tbase + (uint32_t)(row * (RSG * 2) + c * 16),
                           gsrc + (size_t)row * Dc + c * 8);
            }
        }
        cp_commit();
    };

    float acc[4][4][4] = {};

    load_chunk(0, 0);
    load_chunk(1, 1);

    for (int k = 0; k < NCH2; k++) {
        const int s = k & 1;
        cp_wait<1>();
        __syncthreads();

        const __nv_bfloat16* As_hi = smem_bf + s * STAGE_E;
        const __nv_bfloat16* As_lo = As_hi + TILE_E;
        const __nv_bfloat16* Bs_hi = As_lo + TILE_E;
        const __nv_bfloat16* Bs_lo = Bs_hi + TILE_E;

        #pragma unroll
        for (int kk = 0; kk < 4; kk++) {                  // k16 steps over BK=64
            const int eo = kk * 16 + 4 * tg;
            uint32_t ah[4][4], al[4][4], bh[4][2], bl[4][2];
            #pragma unroll
            for (int mi = 0; mi < 4; mi++) {
                const int r = (wm * 64 + mi * 16 + g) * RSG + eo;
                const uint2 h0 = *(const uint2*)(As_hi + r);
                const uint2 h1 = *(const uint2*)(As_hi + r + 8 * RSG);
                const uint2 l0 = *(const uint2*)(As_lo + r);
                const uint2 l1 = *(const uint2*)(As_lo + r + 8 * RSG);
                ah[mi][0] = h0.x; ah[mi][1] = h1.x; ah[mi][2] = h0.y; ah[mi][3] = h1.y;
                al[mi][0] = l0.x; al[mi][1] = l1.x; al[mi][2] = l0.y; al[mi][3] = l1.y;
            }
            #pragma unroll
            for (int ni = 0; ni < 4; ni++) {
                const int r = (wn * 32 + ni * 8 + g) * RSG + eo;
                const uint2 hb = *(const uint2*)(Bs_hi + r);
                const uint2 lb = *(const uint2*)(Bs_lo + r);
                bh[ni][0] = hb.x; bh[ni][1] = hb.y;
                bl[ni][0] = lb.x; bl[ni][1] = lb.y;
            }
            #pragma unroll
            for (int mi = 0; mi < 4; mi++)
                #pragma unroll
                for (int ni = 0; ni < 4; ni++) {
                    mma_bf16(acc[mi][ni], al[mi], bh[ni]);
                    mma_bf16(acc[mi][ni], ah[mi], bl[ni]);
                    mma_bf16(acc[mi][ni], ah[mi], bh[ni]);
                }
        }

        __syncthreads();
        if (k + 2 < NCH2) load_chunk(k + 2, s); else cp_commit();
    }

    #pragma unroll
    for (int mi = 0; mi < 4; mi++) {
        const int row0 = m0 + wm * 64 + mi * 16 + g;
        #pragma unroll
        for (int ni = 0; ni < 4; ni++) {
            const int col = n0 + wn * 32 + ni * 8 + 2 * tg;
            const float2 bv = *(const float2*)&bias[col];
            float2 v0, v1;
            v0.x = acc[mi][ni][0] + bv.x;  v0.y = acc[mi][ni][1] + bv.y;
            v1.x = acc[mi][ni][2] + bv.x;  v1.y = acc[mi][ni][3] + bv.y;
            if (MODE == 0) {
                *(float2*)(Y + (size_t)row0 * Dc + col) = v0;
                *(float2*)(Y + (size_t)(row0 + 8) * Dc + col) = v1;
            } else {
                const int h = col >> 6, d0 = col & 63;
                const int b0i = row0 >> 11, t0 = row0 & 2047;
                const size_t q0 = (((size_t)b0i * Hc + h) * Tc + t0) << 6;
                const int row1 = row0 + 8;
                const int b1i = row1 >> 11, t1 = row1 & 2047;
                const size_t q1 = (((size_t)b1i * Hc + h) * Tc + t1) << 6;
                if (MODE == 1) {
                    *(float2*)(Y + q0 + d0) = v0;
                    *(float2*)(Y + q1 + d0) = v1;
                } else {
                    __nv_bfloat16* Kh = (__nv_bfloat16*)Y;
                    __nv_bfloat16* Kl = (__nv_bfloat16*)Y2;
                    const int dp0 = perm16(d0);
                    __nv_bfloat162 hh, ll;
                    split_bf16(v0.x, hh.x, ll.x);
                    split_bf16(v0.y, hh.y, ll.y);
                    *(__nv_bfloat162*)(Kh + q0 + dp0) = hh;
                    *(__nv_bfloat162*)(Kl + q0 + dp0) = ll;
                    split_bf16(v1.x, hh.x, ll.x);
                    split_bf16(v1.y, hh.y, ll.y);
                    *(__nv_bfloat162*)(Kh + q1 + dp0) = hh;
                    *(__nv_bfloat162*)(Kl + q1 + dp0) = ll;
                }
            }
        }
    }
}

// ---------------------------------------------------------------------------
// split-bf16 flash attention (3-term m16n8k16 for QK^T and PV), causal.
//   CTA: 64 queries, 4 warps; key tiles of 32, 2-stage cp.async.
// ---------------------------------------------------------------------------
constexpr int AQ  = 64;
constexpr int AKT = 32;
constexpr int RSK = 80;                  // K tile row stride (elements)
constexpr int RSV = 48;                  // Vt tile row stride
constexpr int RSP = 48;                  // P tile row stride
constexpr int KT_E = AKT * RSK;          // 2560
constexpr int VT_E = HDc * RSV;          // 3072
constexpr int ASTG_E = 2 * KT_E + 2 * VT_E;  // 11264
constexpr int P_E = 2 * ASTG_E;          // 22528
constexpr int PW_E = 2 * 16 * RSP;       // 1536 per warp (hi+lo)
constexpr int ATTN_SMEM = (P_E + 4 * PW_E) * 2;  // 57344 B

__global__ __launch_bounds__(128, 2)
void attn_bf16(const float* __restrict__ Q,
               const __nv_bfloat16* __restrict__ Khi, const __nv_bfloat16* __restrict__ Klo,
               const __nv_bfloat16* __restrict__ Vthi, const __nv_bfloat16* __restrict__ Vtlo,
               __nv_bfloat16* __restrict__ Ohi, __nv_bfloat16* __restrict__ Olo)
{
    extern __shared__ __align__(16) char asmem[];
    __nv_bfloat16* smem_bf = (__nv_bfloat16*)asmem;
    const uint32_t sb = smem_to_u32(asmem);
    const int tid = threadIdx.x, wid = tid >> 5, lane = tid & 31;
    const int g = lane >> 2, tg = lane & 3;
    const int bh = blockIdx.y;
    const int q0 = (int)(gridDim.x - 1 - blockIdx.x) * AQ;   // longest tiles first
    const int b = bh >> 4, h = bh & 15;
    const int nt = q0 / AKT + 2;

    // Q fragments (from raw f32), scaled by 1/8, split to bf16 hi/lo. Resident.
    uint32_t qhi[4][4], qlo[4][4];
    {
        const float* qb = Q + ((size_t)bh * Tc + q0 + wid * 16) * HDc;
        #pragma unroll
        for (int kk = 0; kk < 4; kk++) {
            const int ks = kk * 16 + 2 * tg;
            const float2 v00 = *(const float2*)&qb[(size_t)g * HDc + ks];
            const float2 v01 = *(const float2*)&qb[(size_t)g * HDc + ks + 8];
            const float2 v10 = *(const float2*)&qb[(size_t)(g + 8) * HDc + ks];
            const float2 v11 = *(const float2*)&qb[(size_t)(g + 8) * HDc + ks + 8];
            __nv_bfloat16 hx, lx, hy, ly;
            split_bf16(v00.x * 0.125f, hx, lx); split_bf16(v00.y * 0.125f, hy, ly);
            qhi[kk][0] = pack2(hx, hy); qlo[kk][0] = pack2(lx, ly);
            split_bf16(v10.x * 0.125f, hx, lx); split_bf16(v10.y * 0.125f, hy, ly);
            qhi[kk][1] = pack2(hx, hy); qlo[kk][1] = pack2(lx, ly);
            split_bf16(v01.x * 0.125f, hx, lx); split_bf16(v01.y * 0.125f, hy, ly);
            qhi[kk][2] = pack2(hx, hy); qlo[kk][2] = pack2(lx, ly);
            split_bf16(v11.x * 0.125f, hx, lx); split_bf16(v11.y * 0.125f, hy, ly);
            qhi[kk][3] = pack2(hx, hy); qlo[kk][3] = pack2(lx, ly);
        }
    }

    auto load_stage = [&](int t_, int s_) {
        const uint32_t base = sb + (uint32_t)(s_ * ASTG_E) * 2;
        const int k0_ = t_ * AKT;
        const size_t kg = ((size_t)bh * Tc + k0_) * HDc;
        const size_t vg = (size_t)bh * HDc * Tc + k0_;
        #pragma unroll
        for (int i = 0; i < 2; i++) {                    // K hi: 256 16B units
            const int u = i * 128 + tid;
            const int r = u >> 3, c = u & 7;
            cp_async16(base + (uint32_t)(r * RSK + c * 8) * 2, Khi + kg + (size_t)r * HDc + c * 8);
        }
        #pragma unroll
        for (int i = 0; i < 2; i++) {                    // K lo
            const int u = i * 128 + tid;
            const int r = u >> 3, c = u & 7;
            cp_async16(base + (uint32_t)(KT_E + r * RSK + c * 8) * 2, Klo + kg + (size_t)r * HDc + c * 8);
        }
        #pragma unroll
        for (int i = 0; i < 2; i++) {                    // V hi: 64 rows x 4 units
            const int u = i * 128 + tid;
            const int r = u >> 2, c = u & 3;
            cp_async16(base + (uint32_t)(2 * KT_E + r * RSV + c * 8) * 2,
                       Vthi + vg + (size_t)r * Tc + c * 8);
        }
        #pragma unroll
        for (int i = 0; i < 2; i++) {                    // V lo
            const int u = i * 128 + tid;
            const int r = u >> 2, c = u & 3;
            cp_async16(base + (uint32_t)(2 * KT_E + VT_E + r * RSV + c * 8) * 2,
                       Vtlo + vg + (size_t)r * Tc + c * 8);
        }
        cp_commit();
    };

    float acc_o[8][4] = {};
    float m0 = -INFINITY, m1 = -INFINITY, l0 = 0.f, l1 = 0.f;
    const int row0 = q0 + wid * 16 + g;

    load_stage(0, 0);
    if (nt > 1) load_stage(1, 1); else cp_commit();

    for (int t = 0; t < nt; t++) {
        const int s = t & 1;
        const int k0 = t * AKT;
        cp_wait<1>();
        __syncthreads();

        const __nv_bfloat16* Ks_hi = smem_bf + s * ASTG_E;
        const __nv_bfloat16* Ks_lo = Ks_hi + KT_E;
        const __nv_bfloat16* Vs_hi = Ks_hi + 2 * KT_E;
        const __nv_bfloat16* Vs_lo = Vs_hi + VT_E;
        __nv_bfloat16* Phi = smem_bf + P_E + wid * PW_E;
        __nv_bfloat16* Plo = Phi + 16 * RSP;

        // ---- S = Q @ K^T (3-term bf16) ----
        float sacc[4][4] = {};
        #pragma unroll
        for (int kk = 0; kk < 4; kk++) {
            #pragma unroll
            for (int n_ = 0; n_ < 4; n_++) {
                const int r = (n_ * 8 + g) * RSK + kk * 16 + 4 * tg;
                const uint2 kh2 = *(const uint2*)(Ks_hi + r);
                const uint2 kl2 = *(const uint2*)(Ks_lo + r);
                uint32_t kh[2] = {kh2.x, kh2.y};
                uint32_t kl[2] = {kl2.x, kl2.y};
                mma_bf16(sacc[n_], qlo[kk], kh);
                mma_bf16(sacc[n_], qhi[kk], kl);
                mma_bf16(sacc[n_], qhi[kk], kh);
            }
        }

        // ---- causal mask (original column order) ----
        if (k0 + AKT - 1 > q0 + wid * 16) {
            #pragma unroll
            for (int n_ = 0; n_ < 4; n_++) {
                const int c0 = k0 + n_ * 8 + 2 * tg;
                if (c0 > row0)     sacc[n_][0] = -1e30f;
                if (c0 + 1 > row0) sacc[n_][1] = -1e30f;
                if (c0 > row0 + 8)     sacc[n_][2] = -1e30f;
                if (c0 + 1 > row0 + 8) sacc[n_][3] = -1e30f;
            }
        }

        // ---- online softmax ----
        float tx0 = sacc[0][0], tx1 = sacc[0][2];
        #pragma unroll
        for (int n_ = 0; n_ < 4; n_++) {
            tx0 = fmaxf(tx0, fmaxf(sacc[n_][0], sacc[n_][1]));
            tx1 = fmaxf(tx1, fmaxf(sacc[n_][2], sacc[n_][3]));
        }
        tx0 = fmaxf(tx0, __shfl_xor_sync(0xffffffffu, tx0, 1));
        tx0 = fmaxf(tx0, __shfl_xor_sync(0xffffffffu, tx0, 2));
        tx1 = fmaxf(tx1, __shfl_xor_sync(0xffffffffu, tx1, 1));
        tx1 = fmaxf(tx1, __shfl_xor_sync(0xffffffffu, tx1, 2));
        const float mn0 = fmaxf(m0, tx0), mn1 = fmaxf(m1, tx1);
        const float c0f = __expf(m0 - mn0), c1f = __expf(m1 - mn1);
        m0 = mn0; m1 = mn1;

        float rs0 = 0.f, rs1 = 0.f;
        #pragma unroll
        for (int n_ = 0; n_ < 4; n_++) {
            const float p0 = __expf(sacc[n_][0] - mn0);
            const float p1 = __expf(sacc[n_][1] - mn0);
            const float p2 = __expf(sacc[n_][2] - mn1);
            const float p3 = __expf(sacc[n_][3] - mn1);
            rs0 += p0 + p1; rs1 += p2 + p3;
            // store P (hi/lo) at pair-permuted key positions
            const int cb = ((n_ >> 1) << 4) + 4 * tg + ((n_ & 1) << 1);
            __nv_bfloat16 h0, l0v, h1, l1v;
            split_bf16(p0, h0, l0v); split_bf16(p1, h1, l1v);
            *(uint32_t*)(Phi + g * RSP + cb) = pack2(h0, h1);
            *(uint32_t*)(Plo + g * RSP + cb) = pack2(l0v, l1v);
            split_bf16(p2, h0, l0v); split_bf16(p3, h1, l1v);
            *(uint32_t*)(Phi + (g + 8) * RSP + cb) = pack2(h0, h1);
            *(uint32_t*)(Plo + (g + 8) * RSP + cb) = pack2(l0v, l1v);
        }
        rs0 += __shfl_xor_sync(0xffffffffu, rs0, 1);
        rs0 += __shfl_xor_sync(0xffffffffu, rs0, 2);
        rs1 += __shfl_xor_sync(0xffffffffu, rs1, 1);
        rs1 += __shfl_xor_sync(0xffffffffu, rs1, 2);
        l0 = l0 * c0f + rs0;
        l1 = l1 * c1f + rs1;

        #pragma unroll
        for (int d8 = 0; d8 < 8; d8++) {
            acc_o[d8][0] *= c0f; acc_o[d8][1] *= c0f;
            acc_o[d8][2] *= c1f; acc_o[d8][3] *= c1f;
        }
        __syncwarp();

        // ---- O += P @ V (3-term bf16) ----
        #pragma unroll
        for (int kc = 0; kc < 2; kc++) {
            const int eo = kc * 16 + 4 * tg;
            const uint2 ph0 = *(const uint2*)(Phi + g * RSP + eo);
            const uint2 ph1 = *(const uint2*)(Phi + (g + 8) * RSP + eo);
            const uint2 pl0 = *(const uint2*)(Plo + g * RSP + eo);
            const uint2 pl1 = *(const uint2*)(Plo + (g + 8) * RSP + eo);
            uint32_t pah[4] = {ph0.x, ph1.x, ph0.y, ph1.y};
            uint32_t pal[4] = {pl0.x, pl1.x, pl0.y, pl1.y};
            #pragma unroll
            for (int d8 = 0; d8 < 8; d8++) {
                const int r = (d8 * 8 + g) * RSV + eo;
                const uint2 vh2 = *(const uint2*)(Vs_hi + r);
                const uint2 vl2 = *(const uint2*)(Vs_lo + r);
                uint32_t vh[2] = {vh2.x, vh2.y};
                uint32_t vl[2] = {vl2.x, vl2.y};
                mma_bf16(acc_o[d8], pal, vh);
                mma_bf16(acc_o[d8], pah, vl);
                mma_bf16(acc_o[d8], pah, vh);
            }
        }
        __syncwarp();

        __syncthreads();
        if (t + 2 < nt) load_stage(t + 2, s); else cp_commit();
    }

    // ---- epilogue: O/l, split hi/lo bf16, merge heads, D-pair-permute ----
    const float il0 = 1.f / l0, il1 = 1.f / l1;
    const size_t ob0 = ((size_t)b * Tc + row0) * Dc + (size_t)h * HDc;
    const size_t ob1 = ob0 + (size_t)8 * Dc;
    #pragma unroll
    for (int d8 = 0; d8 < 8; d8++) {
        const int c = d8 * 8 + 2 * tg;
        const int cp0 = perm16(c);
        const float v0 = acc_o[d8][0] * il0, v1 = acc_o[d8][1] * il0;
        const float v2 = acc_o[d8][2] * il1, v3 = acc_o[d8][3] * il1;
        __nv_bfloat162 hh, ll;
        split_bf16(v0, hh.x, ll.x); split_bf16(v1, hh.y, ll.y);
        *(__nv_bfloat162*)(Ohi + ob0 + cp0) = hh;
        *(__nv_bfloat162*)(Olo + ob0 + cp0) = ll;
        split_bf16(v2, hh.x, ll.x); split_bf16(v3, hh.y, ll.y);
        *(__nv_bfloat162*)(Ohi + ob1 + cp0) = hh;
        *(__nv_bfloat162*)(Olo + ob1 + cp0) = ll;
    }
}

// ---------------------------------------------------------------------------
// Launch
// ---------------------------------------------------------------------------
extern "C" void kernel_launch(void* const* d_in, const int* in_sizes, int n_in,
                              void* d_out, int out_size)
{
    const float* x  = (const float*)d_in[0];
    const float* Wq = (const float*)d_in[1];
    const float* bq = (const float*)d_in[2];
    const float* Wk = (const float*)d_in[3];
    const float* bk = (const float*)d_in[4];
    const float* Wv = (const float*)d_in[5];
    const float* bv = (const float*)d_in[6];
    const float* Wo = (const float*)d_in[7];
    const float* bo = (const float*)d_in[8];
    float* out = (float*)d_out;

    __nv_bfloat16 *Xhi, *Xlo, *Khi, *Klo, *Vthi, *Vtlo, *Ahi, *Alo, *Whi, *Wlo;
    float *Qp, *Vp;
    cudaGetSymbolAddress((void**)&Xhi, g_Xhi);
    cudaGetSymbolAddress((void**)&Xlo, g_Xlo);
    cudaGetSymbolAddress((void**)&Qp, g_Q);
    cudaGetSymbolAddress((void**)&Vp, g_V);
    cudaGetSymbolAddress((void**)&Khi, g_Khi);
    cudaGetSymbolAddress((void**)&Klo, g_Klo);
    cudaGetSymbolAddress((void**)&Vthi, g_Vthi);
    cudaGetSymbolAddress((void**)&Vtlo, g_Vtlo);
    cudaGetSymbolAddress((void**)&Ahi, g_Ahi);
    cudaGetSymbolAddress((void**)&Alo, g_Alo);
    cudaGetSymbolAddress((void**)&Whi, g_Wthi);
    cudaGetSymbolAddress((void**)&Wlo, g_Wtlo);

    cudaFuncSetAttribute(gemm_bf16x3<0>, cudaFuncAttributeMaxDynamicSharedMemorySize, GEMM_SMEM);
    cudaFuncSetAttribute(gemm_bf16x3<1>, cudaFuncAttributeMaxDynamicSharedMemorySize, GEMM_SMEM);
    cudaFuncSetAttribute(gemm_bf16x3<2>, cudaFuncAttributeMaxDynamicSharedMemorySize, GEMM_SMEM);
    cudaFuncSetAttribute(attn_bf16, cudaFuncAttributeMaxDynamicSharedMemorySize, ATTN_SMEM);

    // 1) prep: split+permute X; transpose+split+permute weights
    const int n2 = Mc * Dc / 2;
    split_permK_bf16<<<(n2 + 255) / 256, 256>>>(x, Xhi, Xlo, n2);
    transpose4_split<<<dim3(32, 32, 4), dim3(32, 8)>>>(Wq, Wk, Wv, Wo, Whi, Wlo);

    // 2) Q/K/V projections (split-bf16 tensor cores)
    const dim3 gg(Dc / BN, Mc / BM);   // (8, 32)
    const size_t DD = (size_t)Dc * Dc;
    gemm_bf16x3<1><<<gg, 256, GEMM_SMEM>>>(Xhi, Xlo, Whi + 0 * DD, Wlo + 0 * DD, bq, Qp, nullptr);
    gemm_bf16x3<2><<<gg, 256, GEMM_SMEM>>>(Xhi, Xlo, Whi + 1 * DD, Wlo + 1 * DD, bk,
                                           (float*)Khi, (float*)Klo);
    gemm_bf16x3<1><<<gg, 256, GEMM_SMEM>>>(Xhi, Xlo, Whi + 2 * DD, Wlo + 2 * DD, bv, Vp, nullptr);

    // 3) prep V (transpose + split + t-permute)
    trans_split_V<<<dim3(Tc / 32, HDc / 32, Bc * Hc), dim3(32, 8)>>>(Vp, Vthi, Vtlo);

    // 4) attention
    const dim3 ag(Tc / AQ, Bc * Hc);   // (32, 32)
    attn_bf16<<<ag, 128, ATTN_SMEM>>>(Qp, Khi, Klo, Vthi, Vtlo, Ahi, Alo);

    // 5) output projection -> d_out
    gemm_bf16x3<0><<<gg, 256, GEMM_SMEM>>>(Ahi, Alo, Whi + 3 * DD, Wlo + 3 * DD, bo, out, nullptr);
}

// round 10
// speedup vs baseline: 6.4572x; 1.0664x over previous
#include <cuda_runtime.h>
#include <cuda_bf16.h>
#include <math.h>
#include <stdint.h>

// Problem constants
constexpr int Bc  = 2;
constexpr int Tc  = 2048;
constexpr int Dc  = 1024;
constexpr int Hc  = 16;
constexpr int HDc = 64;
constexpr int Mc  = Bc * Tc;      // 4096

// ---------------------------------------------------------------------------
// Scratch (device globals; no allocations allowed)
// ---------------------------------------------------------------------------
__device__ __nv_bfloat16 g_Xhi[Mc * Dc];             // k-pair-permuted
__device__ __nv_bfloat16 g_Xlo[Mc * Dc];
__device__ float         g_Q[Bc * Hc * Tc * HDc];    // raw f32
__device__ float         g_V[Bc * Hc * Tc * HDc];    // raw f32
__device__ __nv_bfloat16 g_Khi[Bc * Hc * Tc * HDc];  // d-pair-permuted
__device__ __nv_bfloat16 g_Klo[Bc * Hc * Tc * HDc];
__device__ __nv_bfloat16 g_Vthi[Bc * Hc * Tc * HDc]; // [bh][d][t], t-permuted
__device__ __nv_bfloat16 g_Vtlo[Bc * Hc * Tc * HDc];
__device__ __nv_bfloat16 g_Ahi[Mc * Dc];             // D-pair-permuted
__device__ __nv_bfloat16 g_Alo[Mc * Dc];
__device__ __nv_bfloat16 g_Wthi[4 * Dc * Dc];        // [n][k], k-permuted
__device__ __nv_bfloat16 g_Wtlo[4 * Dc * Dc];

// ---------------------------------------------------------------------------
// Helpers
// ---------------------------------------------------------------------------
// pair permutation within 16-blocks: element c -> pair p=(c>>1)&7 goes to
// position fp(p)=2*(p&3)+(p>>2); a thread then reads mma k-pairs (2tg,2tg+1),
// (2tg+8,2tg+9) as 4 contiguous elements at offset 4*tg.
__device__ __host__ __forceinline__ int perm16(int c) {
    const int p = (c >> 1) & 7, e = c & 1;
    const int fp = ((p & 3) << 1) | (p >> 2);
    return (c & ~15) | (fp << 1) | e;
}

__device__ __forceinline__ uint32_t smem_to_u32(const void* p) {
    uint32_t a;
    asm("{ .reg .u64 t; cvta.to.shared.u64 t, %1; cvt.u32.u64 %0, t; }" : "=r"(a) : "l"(p));
    return a;
}

__device__ __forceinline__ void cp_async16(uint32_t saddr, const void* gaddr) {
    asm volatile("cp.async.cg.shared.global [%0], [%1], 16;" :: "r"(saddr), "l"(gaddr));
}
__device__ __forceinline__ void cp_commit() {
    asm volatile("cp.async.commit_group;" ::: "memory");
}
template <int N>
__device__ __forceinline__ void cp_wait() {
    asm volatile("cp.async.wait_group %0;" :: "n"(N) : "memory");
}

// bf16 m16n8k16 mma.sync (sm_80+)
__device__ __forceinline__ void mma_bf16(float* d, const uint32_t* a, const uint32_t* b) {
    asm volatile(
        "mma.sync.aligned.m16n8k16.row.col.f32.bf16.bf16.f32 "
        "{%0,%1,%2,%3}, {%4,%5,%6,%7}, {%8,%9}, {%0,%1,%2,%3};"
        : "+f"(d[0]), "+f"(d[1]), "+f"(d[2]), "+f"(d[3])
        : "r"(a[0]), "r"(a[1]), "r"(a[2]), "r"(a[3]), "r"(b[0]), "r"(b[1]));
}

__device__ __forceinline__ void split_bf16(float v, __nv_bfloat16& h, __nv_bfloat16& l) {
    h = __float2bfloat16_rn(v);
    l = __float2bfloat16_rn(v - __bfloat162float(h));
}
__device__ __forceinline__ uint32_t pack2(__nv_bfloat16 a, __nv_bfloat16 b) {
    __nv_bfloat162 t; t.x = a; t.y = b;
    return *(uint32_t*)&t;
}

// ---------------------------------------------------------------------------
// Prep: split X (f32 [M,1024]) into bf16 hi/lo, k-pair-permuted. 1 pair/thread.
// ---------------------------------------------------------------------------
__global__ __launch_bounds__(256)
void split_permK_bf16(const float* __restrict__ in, __nv_bfloat16* __restrict__ hi,
                      __nv_bfloat16* __restrict__ lo, int n2)
{
    int i = blockIdx.x * 256 + threadIdx.x;
    if (i < n2) {
        const int j = 2 * i;
        const float2 v = *(const float2*)(in + j);
        const int p = (j >> 1) & 7;
        const int newj = (j & ~15) | ((((p & 3) << 1) | (p >> 2)) << 1);
        __nv_bfloat162 h, l;
        split_bf16(v.x, h.x, l.x);
        split_bf16(v.y, h.y, l.y);
        *(__nv_bfloat162*)(hi + newj) = h;
        *(__nv_bfloat162*)(lo + newj) = l;
    }
}

// ---------------------------------------------------------------------------
// Prep: per-head transpose+split of V: Vt[bh][d][perm16(t)] = split(V[bh][t][d])
// ---------------------------------------------------------------------------
__global__ __launch_bounds__(256)
void trans_split_V(const float* __restrict__ V, __nv_bfloat16* __restrict__ Thi,
                   __nv_bfloat16* __restrict__ Tlo)
{
    __shared__ float tile[32][33];
    const int bh = blockIdx.z;
    const int t0 = blockIdx.x * 32, d0 = blockIdx.y * 32;
    const int tx = threadIdx.x, ty = threadIdx.y;
    const float* src = V + (size_t)bh * Tc * HDc;
    #pragma unroll
    for (int j = 0; j < 32; j += 8)
        tile[ty + j][tx] = src[(size_t)(t0 + ty + j) * HDc + d0 + tx];
    __syncthreads();
    __nv_bfloat16* dh = Thi + (size_t)bh * HDc * Tc;
    __nv_bfloat16* dl = Tlo + (size_t)bh * HDc * Tc;
    const int txp = t0 + perm16(tx);
    #pragma unroll
    for (int j = 0; j < 32; j += 8) {
        __nv_bfloat16 h, l;
        split_bf16(tile[tx][ty + j], h, l);
        dh[(size_t)(d0 + ty + j) * Tc + txp] = h;
        dl[(size_t)(d0 + ty + j) * Tc + txp] = l;
    }
}

// ---------------------------------------------------------------------------
// Weight transpose + split + k-pair perm: Wt[n][perm16(k)] = split(W[k][n])
// ---------------------------------------------------------------------------
__global__ __launch_bounds__(256)
void transpose4_split(const float* __restrict__ W0, const float* __restrict__ W1,
                      const float* __restrict__ W2, const float* __restrict__ W3,
                      __nv_bfloat16* __restrict__ Thi, __nv_bfloat16* __restrict__ Tlo)
{
    __shared__ float tile[32][33];
    const int z = blockIdx.z;
    const float* W = (z == 0) ? W0 : (z == 1) ? W1 : (z == 2) ? W2 : W3;
    const size_t zoff = (size_t)z * Dc * Dc;

    const int tx = threadIdx.x, ty = threadIdx.y;
    int x = blockIdx.x * 32 + tx;
    int y = blockIdx.y * 32 + ty;
    #pragma unroll
    for (int j = 0; j < 32; j += 8)
        tile[ty + j][tx] = W[(size_t)(y + j) * Dc + x];
    __syncthreads();
    const int xp = blockIdx.y * 32 + perm16(tx);   // permuted k column
    y = blockIdx.x * 32 + ty;
    #pragma unroll
    for (int j = 0; j < 32; j += 8) {
        __nv_bfloat16 h, l;
        split_bf16(tile[tx][ty + j], h, l);
        Thi[zoff + (size_t)(y + j) * Dc + xp] = h;
        Tlo[zoff + (size_t)(y + j) * Dc + xp] = l;
    }
}

// ---------------------------------------------------------------------------
// split-bf16 (3-term) GEMM (R9-proven, unchanged):  Y = X @ Wt^T + bias
// ---------------------------------------------------------------------------
constexpr int BM = 128, BN = 128, BKC2 = 64;
constexpr int NCH2 = Dc / BKC2;          // 16
constexpr int RSG = 80;                  // bf16 elements per smem row (160B)
constexpr int TILE_E = BM * RSG;         // 10240 elements
constexpr int STAGE_E = 4 * TILE_E;      // Ahi, Alo, Bhi, Blo
constexpr int GEMM_SMEM = 2 * STAGE_E * 2;   // 163840 B

template <int MODE>
__global__ __launch_bounds__(256, 1)
void gemm_bf16x3(const __nv_bfloat16* __restrict__ Xhi, const __nv_bfloat16* __restrict__ Xlo,
                 const __nv_bfloat16* __restrict__ Whi, const __nv_bfloat16* __restrict__ Wlo,
                 const float* __restrict__ bias,
                 float* __restrict__ Y, float* __restrict__ Y2)
{
    extern __shared__ __align__(16) char smem_raw[];
    __nv_bfloat16* smem_bf = (__nv_bfloat16*)smem_raw;
    const uint32_t sb = smem_to_u32(smem_raw);
    const int tid = threadIdx.x;
    const int wid = tid >> 5, lane = tid & 31;
    const int g = lane >> 2, tg = lane & 3;
    const int wm = wid & 1;
    const int wn = wid >> 1;
    const int m0 = blockIdx.y * BM;
    const int n0 = blockIdx.x * BN;

    auto load_chunk = [&](int k, int s) {
        const uint32_t sbase = sb + (uint32_t)s * STAGE_E * 2;
        const size_t aoff = (size_t)m0 * Dc + k * BKC2;
        const size_t boff = (size_t)n0 * Dc + k * BKC2;
        const __nv_bfloat16* srcs[4] = {Xhi + aoff, Xlo + aoff, Whi + boff, Wlo + boff};
        #pragma unroll
        for (int t = 0; t < 4; t++) {
            const __nv_bfloat16* gsrc = srcs[t];
            const uint32_t tbase = sbase + (uint32_t)t * TILE_E * 2;
            #pragma unroll
            for (int i = 0; i < 4; i++) {
                const int u = i * 256 + tid;
                const int row = u >> 3, c = u & 7;
                cp_async16(tbase + (uint32_t)(row * (RSG * 2) + c * 16),
                           gsrc + (size_t)row * Dc + c * 8);
            }
        }
        cp_commit();
    };

    float acc[4][4][4] = {};

    load_chunk(0, 0);
    load_chunk(1, 1);

    for (int k = 0; k < NCH2; k++) {
        const int s = k & 1;
        cp_wait<1>();
        __syncthreads();

        const __nv_bfloat16* As_hi = smem_bf + s * STAGE_E;
        const __nv_bfloat16* As_lo = As_hi + TILE_E;
        const __nv_bfloat16* Bs_hi = As_lo + TILE_E;
        const __nv_bfloat16* Bs_lo = Bs_hi + TILE_E;

        #pragma unroll
        for (int kk = 0; kk < 4; kk++) {
            const int eo = kk * 16 + 4 * tg;
            uint32_t ah[4][4], al[4][4], bh[4][2], bl[4][2];
            #pragma unroll
            for (int mi = 0; mi < 4; mi++) {
                const int r = (wm * 64 + mi * 16 + g) * RSG + eo;
                const uint2 h0 = *(const uint2*)(As_hi + r);
                const uint2 h1 = *(const uint2*)(As_hi + r + 8 * RSG);
                const uint2 l0 = *(const uint2*)(As_lo + r);
                const uint2 l1 = *(const uint2*)(As_lo + r + 8 * RSG);
                ah[mi][0] = h0.x; ah[mi][1] = h1.x; ah[mi][2] = h0.y; ah[mi][3] = h1.y;
                al[mi][0] = l0.x; al[mi][1] = l1.x; al[mi][2] = l0.y; al[mi][3] = l1.y;
            }
            #pragma unroll
            for (int ni = 0; ni < 4; ni++) {
                const int r = (wn * 32 + ni * 8 + g) * RSG + eo;
                const uint2 hb = *(const uint2*)(Bs_hi + r);
                const uint2 lb = *(const uint2*)(Bs_lo + r);
                bh[ni][0] = hb.x; bh[ni][1] = hb.y;
                bl[ni][0] = lb.x; bl[ni][1] = lb.y;
            }
            #pragma unroll
            for (int mi = 0; mi < 4; mi++)
                #pragma unroll
                for (int ni = 0; ni < 4; ni++) {
                    mma_bf16(acc[mi][ni], al[mi], bh[ni]);
                    mma_bf16(acc[mi][ni], ah[mi], bl[ni]);
                    mma_bf16(acc[mi][ni], ah[mi], bh[ni]);
                }
        }

        __syncthreads();
        if (k + 2 < NCH2) load_chunk(k + 2, s); else cp_commit();
    }

    #pragma unroll
    for (int mi = 0; mi < 4; mi++) {
        const int row0 = m0 + wm * 64 + mi * 16 + g;
        #pragma unroll
        for (int ni = 0; ni < 4; ni++) {
            const int col = n0 + wn * 32 + ni * 8 + 2 * tg;
            const float2 bv = *(const float2*)&bias[col];
            float2 v0, v1;
            v0.x = acc[mi][ni][0] + bv.x;  v0.y = acc[mi][ni][1] + bv.y;
            v1.x = acc[mi][ni][2] + bv.x;  v1.y = acc[mi][ni][3] + bv.y;
            if (MODE == 0) {
                *(float2*)(Y + (size_t)row0 * Dc + col) = v0;
                *(float2*)(Y + (size_t)(row0 + 8) * Dc + col) = v1;
            } else {
                const int h = col >> 6, d0 = col & 63;
                const int b0i = row0 >> 11, t0 = row0 & 2047;
                const size_t q0 = (((size_t)b0i * Hc + h) * Tc + t0) << 6;
                const int row1 = row0 + 8;
                const int b1i = row1 >> 11, t1 = row1 & 2047;
                const size_t q1 = (((size_t)b1i * Hc + h) * Tc + t1) << 6;
                if (MODE == 1) {
                    *(float2*)(Y + q0 + d0) = v0;
                    *(float2*)(Y + q1 + d0) = v1;
                } else {
                    __nv_bfloat16* Kh = (__nv_bfloat16*)Y;
                    __nv_bfloat16* Kl = (__nv_bfloat16*)Y2;
                    const int dp0 = perm16(d0);
                    __nv_bfloat162 hh, ll;
                    split_bf16(v0.x, hh.x, ll.x);
                    split_bf16(v0.y, hh.y, ll.y);
                    *(__nv_bfloat162*)(Kh + q0 + dp0) = hh;
                    *(__nv_bfloat162*)(Kl + q0 + dp0) = ll;
                    split_bf16(v1.x, hh.x, ll.x);
                    split_bf16(v1.y, hh.y, ll.y);
                    *(__nv_bfloat162*)(Kh + q1 + dp0) = hh;
                    *(__nv_bfloat162*)(Kl + q1 + dp0) = ll;
                }
            }
        }
    }
}

// ---------------------------------------------------------------------------
// split-bf16 flash attention, causal. AQ=64 queries, AKT=64 keys per tile,
// 4 warps. P kept in REGISTERS (C-frag == A-frag layout); no P smem staging.
// ---------------------------------------------------------------------------
constexpr int AQ  = 64;
constexpr int AKT = 64;
constexpr int RSK = 80;                  // K tile row stride (elements): rows=key
constexpr int RSV = 80;                  // Vt tile row stride: rows=d
constexpr int KT_E = AKT * RSK;          // 5120
constexpr int VT_E = HDc * RSV;          // 5120
constexpr int ASTG_E = 2 * KT_E + 2 * VT_E;  // 20480 elements
constexpr int ATTN_SMEM = 2 * ASTG_E * 2;    // 81920 B

__global__ __launch_bounds__(128, 2)
void attn_bf16(const float* __restrict__ Q,
               const __nv_bfloat16* __restrict__ Khi, const __nv_bfloat16* __restrict__ Klo,
               const __nv_bfloat16* __restrict__ Vthi, const __nv_bfloat16* __restrict__ Vtlo,
               __nv_bfloat16* __restrict__ Ohi, __nv_bfloat16* __restrict__ Olo)
{
    extern __shared__ __align__(16) char asmem[];
    __nv_bfloat16* smem_bf = (__nv_bfloat16*)asmem;
    const uint32_t sb = smem_to_u32(asmem);
    const int tid = threadIdx.x, wid = tid >> 5, lane = tid & 31;
    const int g = lane >> 2, tg = lane & 3;
    const int bh = blockIdx.y;
    const int q0 = (int)(gridDim.x - 1 - blockIdx.x) * AQ;   // longest tiles first
    const int b = bh >> 4, h = bh & 15;
    const int nt = q0 / AKT + 1;

    // Q fragments (from raw f32), scaled by 1/8, split to bf16 hi/lo. Resident.
    uint32_t qhi[4][4], qlo[4][4];
    {
        const float* qb = Q + ((size_t)bh * Tc + q0 + wid * 16) * HDc;
        #pragma unroll
        for (int kk = 0; kk < 4; kk++) {
            const int ks = kk * 16 + 2 * tg;
            const float2 v00 = *(const float2*)&qb[(size_t)g * HDc + ks];
            const float2 v01 = *(const float2*)&qb[(size_t)g * HDc + ks + 8];
            const float2 v10 = *(const float2*)&qb[(size_t)(g + 8) * HDc + ks];
            const float2 v11 = *(const float2*)&qb[(size_t)(g + 8) * HDc + ks + 8];
            __nv_bfloat16 hx, lx, hy, ly;
            split_bf16(v00.x * 0.125f, hx, lx); split_bf16(v00.y * 0.125f, hy, ly);
            qhi[kk][0] = pack2(hx, hy); qlo[kk][0] = pack2(lx, ly);
            split_bf16(v10.x * 0.125f, hx, lx); split_bf16(v10.y * 0.125f, hy, ly);
            qhi[kk][1] = pack2(hx, hy); qlo[kk][1] = pack2(lx, ly);
            split_bf16(v01.x * 0.125f, hx, lx); split_bf16(v01.y * 0.125f, hy, ly);
            qhi[kk][2] = pack2(hx, hy); qlo[kk][2] = pack2(lx, ly);
            split_bf16(v11.x * 0.125f, hx, lx); split_bf16(v11.y * 0.125f, hy, ly);
            qhi[kk][3] = pack2(hx, hy); qlo[kk][3] = pack2(lx, ly);
        }
    }

    auto load_stage = [&](int t_, int s_) {
        const uint32_t base = sb + (uint32_t)(s_ * ASTG_E) * 2;
        const int k0_ = t_ * AKT;
        const size_t kg = ((size_t)bh * Tc + k0_) * HDc;
        const size_t vg = (size_t)bh * HDc * Tc + k0_;
        #pragma unroll
        for (int i = 0; i < 4; i++) {                    // K hi: 64 rows x 8 units
            const int u = i * 128 + tid;
            const int r = u >> 3, c = u & 7;
            cp_async16(base + (uint32_t)(r * RSK + c * 8) * 2, Khi + kg + (size_t)r * HDc + c * 8);
        }
        #pragma unroll
        for (int i = 0; i < 4; i++) {                    // K lo
            const int u = i * 128 + tid;
            const int r = u >> 3, c = u & 7;
            cp_async16(base + (uint32_t)(KT_E + r * RSK + c * 8) * 2, Klo + kg + (size_t)r * HDc + c * 8);
        }
        #pragma unroll
        for (int i = 0; i < 4; i++) {                    // V hi: 64 rows x 8 units
            const int u = i * 128 + tid;
            const int r = u >> 3, c = u & 7;
            cp_async16(base + (uint32_t)(2 * KT_E + r * RSV + c * 8) * 2,
                       Vthi + vg + (size_t)r * Tc + c * 8);
        }
        #pragma unroll
        for (int i = 0; i < 4; i++) {                    // V lo
            const int u = i * 128 + tid;
            const int r = u >> 3, c = u & 7;
            cp_async16(base + (uint32_t)(2 * KT_E + VT_E + r * RSV + c * 8) * 2,
                       Vtlo + vg + (size_t)r * Tc + c * 8);
        }
        cp_commit();
    };

    float acc_o[8][4] = {};
    float m0 = -INFINITY, m1 = -INFINITY, l0 = 0.f, l1 = 0.f;
    const int row0 = q0 + wid * 16 + g;

    load_stage(0, 0);
    if (nt > 1) load_stage(1, 1); else cp_commit();

    for (int t = 0; t < nt; t++) {
        const int s = t & 1;
        const int k0 = t * AKT;
        cp_wait<1>();
        __syncthreads();

        const __nv_bfloat16* Ks_hi = smem_bf + s * ASTG_E;
        const __nv_bfloat16* Ks_lo = Ks_hi + KT_E;
        const __nv_bfloat16* Vs_hi = Ks_hi + 2 * KT_E;
        const __nv_bfloat16* Vs_lo = Vs_hi + VT_E;

        // ---- S = Q @ K^T (3-term bf16), 8 n-tiles of 8 keys ----
        float sacc[8][4] = {};
        #pragma unroll
        for (int kk = 0; kk < 4; kk++) {
            #pragma unroll
            for (int n_ = 0; n_ < 8; n_++) {
                const int r = (n_ * 8 + g) * RSK + kk * 16 + 4 * tg;
                const uint2 kh2 = *(const uint2*)(Ks_hi + r);
                const uint2 kl2 = *(const uint2*)(Ks_lo + r);
                uint32_t kh[2] = {kh2.x, kh2.y};
                uint32_t kl[2] = {kl2.x, kl2.y};
                mma_bf16(sacc[n_], qlo[kk], kh);
                mma_bf16(sacc[n_], qhi[kk], kl);
                mma_bf16(sacc[n_], qhi[kk], kh);
            }
        }

        // ---- causal mask (diagonal tile only: k0 == q0) ----
        if (k0 + AKT - 1 > q0 + wid * 16) {
            #pragma unroll
            for (int n_ = 0; n_ < 8; n_++) {
                const int c0 = k0 + n_ * 8 + 2 * tg;
                if (c0 > row0)     sacc[n_][0] = -1e30f;
                if (c0 + 1 > row0) sacc[n_][1] = -1e30f;
                if (c0 > row0 + 8)     sacc[n_][2] = -1e30f;
                if (c0 + 1 > row0 + 8) sacc[n_][3] = -1e30f;
            }
        }

        // ---- online softmax; p replaces sacc in place ----
        float tx0 = sacc[0][0], tx1 = sacc[0][2];
        #pragma unroll
        for (int n_ = 0; n_ < 8; n_++) {
            tx0 = fmaxf(tx0, fmaxf(sacc[n_][0], sacc[n_][1]));
            tx1 = fmaxf(tx1, fmaxf(sacc[n_][2], sacc[n_][3]));
        }
        tx0 = fmaxf(tx0, __shfl_xor_sync(0xffffffffu, tx0, 1));
        tx0 = fmaxf(tx0, __shfl_xor_sync(0xffffffffu, tx0, 2));
        tx1 = fmaxf(tx1, __shfl_xor_sync(0xffffffffu, tx1, 1));
        tx1 = fmaxf(tx1, __shfl_xor_sync(0xffffffffu, tx1, 2));
        const float mn0 = fmaxf(m0, tx0), mn1 = fmaxf(m1, tx1);
        const float c0f = __expf(m0 - mn0), c1f = __expf(m1 - mn1);
        m0 = mn0; m1 = mn1;

        float rs0 = 0.f, rs1 = 0.f;
        #pragma unroll
        for (int n_ = 0; n_ < 8; n_++) {
            sacc[n_][0] = __expf(sacc[n_][0] - mn0);
            sacc[n_][1] = __expf(sacc[n_][1] - mn0);
            sacc[n_][2] = __expf(sacc[n_][2] - mn1);
            sacc[n_][3] = __expf(sacc[n_][3] - mn1);
            rs0 += sacc[n_][0] + sacc[n_][1];
            rs1 += sacc[n_][2] + sacc[n_][3];
        }
        rs0 += __shfl_xor_sync(0xffffffffu, rs0, 1);
        rs0 += __shfl_xor_sync(0xffffffffu, rs0, 2);
        rs1 += __shfl_xor_sync(0xffffffffu, rs1, 1);
        rs1 += __shfl_xor_sync(0xffffffffu, rs1, 2);
        l0 = l0 * c0f + rs0;
        l1 = l1 * c1f + rs1;

        #pragma unroll
        for (int d8 = 0; d8 < 8; d8++) {
            acc_o[d8][0] *= c0f; acc_o[d8][1] *= c0f;
            acc_o[d8][2] *= c1f; acc_o[d8][3] *= c1f;
        }

        // ---- O += P @ V : P A-frags built directly from sacc registers ----
        #pragma unroll
        for (int kk = 0; kk < 4; kk++) {
            uint32_t pah[4], pal[4];
            __nv_bfloat16 h0, l0b, h1, l1b;
            split_bf16(sacc[2*kk][0], h0, l0b); split_bf16(sacc[2*kk][1], h1, l1b);
            pah[0] = pack2(h0, h1); pal[0] = pack2(l0b, l1b);
            split_bf16(sacc[2*kk][2], h0, l0b); split_bf16(sacc[2*kk][3], h1, l1b);
            pah[1] = pack2(h0, h1); pal[1] = pack2(l0b, l1b);
            split_bf16(sacc[2*kk+1][0], h0, l0b); split_bf16(sacc[2*kk+1][1], h1, l1b);
            pah[2] = pack2(h0, h1); pal[2] = pack2(l0b, l1b);
            split_bf16(sacc[2*kk+1][2], h0, l0b); split_bf16(sacc[2*kk+1][3], h1, l1b);
            pah[3] = pack2(h0, h1); pal[3] = pack2(l0b, l1b);
            #pragma unroll
            for (int d8 = 0; d8 < 8; d8++) {
                const int r = (d8 * 8 + g) * RSV + kk * 16 + 4 * tg;
                const uint2 vh2 = *(const uint2*)(Vs_hi + r);
                const uint2 vl2 = *(const uint2*)(Vs_lo + r);
                uint32_t vh[2] = {vh2.x, vh2.y};
                uint32_t vl[2] = {vl2.x, vl2.y};
                mma_bf16(acc_o[d8], pal, vh);
                mma_bf16(acc_o[d8], pah, vl);
                mma_bf16(acc_o[d8], pah, vh);
            }
        }

        __syncthreads();
        if (t + 2 < nt) load_stage(t + 2, s); else cp_commit();
    }

    // ---- epilogue: O/l, split hi/lo bf16, merge heads, D-pair-permute ----
    const float il0 = 1.f / l0, il1 = 1.f / l1;
    const size_t ob0 = ((size_t)b * Tc + row0) * Dc + (size_t)h * HDc;
    const size_t ob1 = ob0 + (size_t)8 * Dc;
    #pragma unroll
    for (int d8 = 0; d8 < 8; d8++) {
        const int c = d8 * 8 + 2 * tg;
        const int cp0 = perm16(c);
        const float v0 = acc_o[d8][0] * il0, v1 = acc_o[d8][1] * il0;
        const float v2 = acc_o[d8][2] * il1, v3 = acc_o[d8][3] * il1;
        __nv_bfloat162 hh, ll;
        split_bf16(v0, hh.x, ll.x); split_bf16(v1, hh.y, ll.y);
        *(__nv_bfloat162*)(Ohi + ob0 + cp0) = hh;
        *(__nv_bfloat162*)(Olo + ob0 + cp0) = ll;
        split_bf16(v2, hh.x, ll.x); split_bf16(v3, hh.y, ll.y);
        *(__nv_bfloat162*)(Ohi + ob1 + cp0) = hh;
        *(__nv_bfloat162*)(Olo + ob1 + cp0) = ll;
    }
}

// ---------------------------------------------------------------------------
// Launch
// ---------------------------------------------------------------------------
extern "C" void kernel_launch(void* const* d_in, const int* in_sizes, int n_in,
                              void* d_out, int out_size)
{
    const float* x  = (const float*)d_in[0];
    const float* Wq = (const float*)d_in[1];
    const float* bq = (const float*)d_in[2];
    const float* Wk = (const float*)d_in[3];
    const float* bk = (const float*)d_in[4];
    const float* Wv = (const float*)d_in[5];
    const float* bv = (const float*)d_in[6];
    const float* Wo = (const float*)d_in[7];
    const float* bo = (const float*)d_in[8];
    float* out = (float*)d_out;

    __nv_bfloat16 *Xhi, *Xlo, *Khi, *Klo, *Vthi, *Vtlo, *Ahi, *Alo, *Whi, *Wlo;
    float *Qp, *Vp;
    cudaGetSymbolAddress((void**)&Xhi, g_Xhi);
    cudaGetSymbolAddress((void**)&Xlo, g_Xlo);
    cudaGetSymbolAddress((void**)&Qp, g_Q);
    cudaGetSymbolAddress((void**)&Vp, g_V);
    cudaGetSymbolAddress((void**)&Khi, g_Khi);
    cudaGetSymbolAddress((void**)&Klo, g_Klo);
    cudaGetSymbolAddress((void**)&Vthi, g_Vthi);
    cudaGetSymbolAddress((void**)&Vtlo, g_Vtlo);
    cudaGetSymbolAddress((void**)&Ahi, g_Ahi);
    cudaGetSymbolAddress((void**)&Alo, g_Alo);
    cudaGetSymbolAddress((void**)&Whi, g_Wthi);
    cudaGetSymbolAddress((void**)&Wlo, g_Wtlo);

    cudaFuncSetAttribute(gemm_bf16x3<0>, cudaFuncAttributeMaxDynamicSharedMemorySize, GEMM_SMEM);
    cudaFuncSetAttribute(gemm_bf16x3<1>, cudaFuncAttributeMaxDynamicSharedMemorySize, GEMM_SMEM);
    cudaFuncSetAttribute(gemm_bf16x3<2>, cudaFuncAttributeMaxDynamicSharedMemorySize, GEMM_SMEM);
    cudaFuncSetAttribute(attn_bf16, cudaFuncAttributeMaxDynamicSharedMemorySize, ATTN_SMEM);

    // 1) prep: split+permute X; transpose+split+permute weights
    const int n2 = Mc * Dc / 2;
    split_permK_bf16<<<(n2 + 255) / 256, 256>>>(x, Xhi, Xlo, n2);
    transpose4_split<<<dim3(32, 32, 4), dim3(32, 8)>>>(Wq, Wk, Wv, Wo, Whi, Wlo);

    // 2) Q/K/V projections (split-bf16 tensor cores)
    const dim3 gg(Dc / BN, Mc / BM);   // (8, 32)
    const size_t DD = (size_t)Dc * Dc;
    gemm_bf16x3<1><<<gg, 256, GEMM_SMEM>>>(Xhi, Xlo, Whi + 0 * DD, Wlo + 0 * DD, bq, Qp, nullptr);
    gemm_bf16x3<2><<<gg, 256, GEMM_SMEM>>>(Xhi, Xlo, Whi + 1 * DD, Wlo + 1 * DD, bk,
                                           (float*)Khi, (float*)Klo);
    gemm_bf16x3<1><<<gg, 256, GEMM_SMEM>>>(Xhi, Xlo, Whi + 2 * DD, Wlo + 2 * DD, bv, Vp, nullptr);

    // 3) prep V (transpose + split + t-permute)
    trans_split_V<<<dim3(Tc / 32, HDc / 32, Bc * Hc), dim3(32, 8)>>>(Vp, Vthi, Vtlo);

    // 4) attention (P-in-registers, AKT=64)
    const dim3 ag(Tc / AQ, Bc * Hc);   // (32, 32)
    attn_bf16<<<ag, 128, ATTN_SMEM>>>(Qp, Khi, Klo, Vthi, Vtlo, Ahi, Alo);

    // 5) output projection -> d_out
    gemm_bf16x3<0><<<gg, 256, GEMM_SMEM>>>(Ahi, Alo, Whi + 3 * DD, Wlo + 3 * DD, bo, out, nullptr);
}